// round 1
// baseline (speedup 1.0000x reference)
#include <cuda_runtime.h>
#include <cuda_bf16.h>
#include <math.h>

#define T_LEN 4096
#define DM 1024
#define NH 16
#define HD 64
#define WINDOW 1024
#define SCALE_F 0.12f
#define EPS_F 1e-6f

// Scratch (static __device__ — no allocations allowed)
__device__ float g_qkv[(size_t)T_LEN * 3 * DM];        // 48 MB
__device__ float g_q[(size_t)NH * T_LEN * HD];          // 16 MB
__device__ float g_k[(size_t)NH * T_LEN * HD];
__device__ float g_v[(size_t)NH * T_LEN * HD];
__device__ float g_att[(size_t)T_LEN * DM];             // 16 MB

// ---------------------------------------------------------------------------
// C[M,N] = A[M,K] @ B[N,K]^T   (both operands K-major, fp32)
// 128x128 tile, BK=8, 256 threads, 8x8 microtile per thread.
// ---------------------------------------------------------------------------
__global__ __launch_bounds__(256) void gemm_nt(const float* __restrict__ A,
                                               const float* __restrict__ B,
                                               float* __restrict__ C,
                                               int M, int N, int K)
{
    __shared__ float As[8][128];
    __shared__ float Bs[8][128];
    int tid = threadIdx.x;
    int tx = tid & 15;
    int ty = tid >> 4;
    int row0 = blockIdx.y * 128;
    int col0 = blockIdx.x * 128;

    float acc[8][8];
#pragma unroll
    for (int i = 0; i < 8; i++)
#pragma unroll
        for (int j = 0; j < 8; j++) acc[i][j] = 0.f;

    for (int k0 = 0; k0 < K; k0 += 8) {
#pragma unroll
        for (int i = 0; i < 4; i++) {
            int e = tid + i * 256;     // 0..1023
            int r = e >> 3, c = e & 7;
            As[c][r] = A[(size_t)(row0 + r) * K + k0 + c];
            Bs[c][r] = B[(size_t)(col0 + r) * K + k0 + c];
        }
        __syncthreads();
#pragma unroll
        for (int kk = 0; kk < 8; kk++) {
            float4 a0 = *(const float4*)&As[kk][ty * 8];
            float4 a1 = *(const float4*)&As[kk][ty * 8 + 4];
            float4 b0 = *(const float4*)&Bs[kk][tx * 8];
            float4 b1 = *(const float4*)&Bs[kk][tx * 8 + 4];
            float a[8] = {a0.x, a0.y, a0.z, a0.w, a1.x, a1.y, a1.z, a1.w};
            float b[8] = {b0.x, b0.y, b0.z, b0.w, b1.x, b1.y, b1.z, b1.w};
#pragma unroll
            for (int i = 0; i < 8; i++)
#pragma unroll
                for (int j = 0; j < 8; j++) acc[i][j] += a[i] * b[j];
        }
        __syncthreads();
    }
#pragma unroll
    for (int i = 0; i < 8; i++) {
        size_t ro = (size_t)(row0 + ty * 8 + i) * N + col0 + tx * 8;
#pragma unroll
        for (int j = 0; j < 8; j++) C[ro + j] = acc[i][j];
    }
}

// ---------------------------------------------------------------------------
// Per (head, token): RMSNorm q,k; RoPE first 32 dims; v *= 0.5.
// One warp per (h,t); lane l owns dims {2l, 2l+1} (exactly one RoPE pair).
// ---------------------------------------------------------------------------
__global__ __launch_bounds__(128) void qkv_prep(const float* __restrict__ qw,
                                                const float* __restrict__ kw,
                                                const float* __restrict__ cosb,
                                                const float* __restrict__ sinb)
{
    int warp = threadIdx.x >> 5;
    int lane = threadIdx.x & 31;
    int idx = blockIdx.x * 4 + warp;       // 0 .. NH*T-1
    int h = idx >> 12;                      // idx / 4096
    int t = idx & 4095;

    const float* rowbase = g_qkv + (size_t)t * (3 * DM) + h * HD;
    float2 qv = ((const float2*)rowbase)[lane];
    float2 kv = ((const float2*)(rowbase + DM))[lane];
    float2 vv = ((const float2*)(rowbase + 2 * DM))[lane];

    float sq = qv.x * qv.x + qv.y * qv.y;
    float sk = kv.x * kv.x + kv.y * kv.y;
#pragma unroll
    for (int off = 16; off; off >>= 1) {
        sq += __shfl_xor_sync(0xffffffffu, sq, off);
        sk += __shfl_xor_sync(0xffffffffu, sk, off);
    }
    float rq = rsqrtf(sq * (1.f / 64.f) + EPS_F);
    float rk = rsqrtf(sk * (1.f / 64.f) + EPS_F);

    int d0 = lane * 2;
    float q0 = qv.x * rq * qw[d0], q1 = qv.y * rq * qw[d0 + 1];
    float k0 = kv.x * rk * kw[d0], k1 = kv.y * rk * kw[d0 + 1];

    if (lane < 16) {   // dims 0..31 rotated; pair index = lane
        float c = cosb[t * 16 + lane];
        float s = sinb[t * 16 + lane];
        float e = q0, o = q1;
        q0 = e * c - o * s;  q1 = e * s + o * c;
        e = k0; o = k1;
        k0 = e * c - o * s;  k1 = e * s + o * c;
    }

    size_t base = ((size_t)h * T_LEN + t) * HD + d0;
    *(float2*)&g_q[base] = make_float2(q0, q1);
    *(float2*)&g_k[base] = make_float2(k0, k1);
    *(float2*)&g_v[base] = make_float2(vv.x * 0.5f, vv.y * 0.5f);
}

// ---------------------------------------------------------------------------
// Sliding-window attention. Block = (head, 32 queries). Online softmax over
// 32-key chunks. 256 threads = 32 queries x 8 threads; each thread owns 8
// output dims. SMEM rows padded to 68 floats (bank-conflict-free float4).
// ---------------------------------------------------------------------------
__global__ __launch_bounds__(256) void attn_kernel()
{
    __shared__ float qs[32][68];
    __shared__ float ks[32][68];
    __shared__ float vs[32][68];
    __shared__ float ps[32][33];

    int h = blockIdx.y;
    int q0 = blockIdx.x * 32;
    int tid = threadIdx.x;

    const float* qb = g_q + (size_t)h * T_LEN * HD;
    const float* kb = g_k + (size_t)h * T_LEN * HD;
    const float* vb = g_v + (size_t)h * T_LEN * HD;

    for (int i = tid; i < 32 * HD; i += 256) {
        int r = i >> 6, d = i & 63;
        qs[r][d] = qb[(size_t)(q0 + r) * HD + d];
    }

    int g = tid >> 3;      // query within tile
    int l = tid & 7;       // lane within query-group
    int t = q0 + g;

    float m = -1e30f, lsum = 0.f;
    float o[8];
#pragma unroll
    for (int i = 0; i < 8; i++) o[i] = 0.f;

    int c0 = (q0 >= WINDOW) ? (q0 - WINDOW) : 0;

    for (int s0 = c0; s0 < q0 + 32; s0 += 32) {
        __syncthreads();   // prior chunk's vs reads done
        for (int i = tid; i < 32 * HD; i += 256) {
            int r = i >> 6, d = i & 63;
            ks[r][d] = kb[(size_t)(s0 + r) * HD + d];
            vs[r][d] = vb[(size_t)(s0 + r) * HD + d];
        }
        __syncthreads();

        // scores for keys l*4 .. l*4+3
        float sc[4] = {0.f, 0.f, 0.f, 0.f};
        const float4* q4 = (const float4*)qs[g];
#pragma unroll
        for (int d4 = 0; d4 < 16; d4++) {
            float4 qv = q4[d4];
#pragma unroll
            for (int j = 0; j < 4; j++) {
                float4 kk4 = *(const float4*)&ks[l * 4 + j][d4 * 4];
                sc[j] += qv.x * kk4.x + qv.y * kk4.y + qv.z * kk4.z + qv.w * kk4.w;
            }
        }

        float cmax = -1e30f;
        bool al[4];
#pragma unroll
        for (int j = 0; j < 4; j++) {
            int s = s0 + l * 4 + j;
            int diff = t - s;
            al[j] = (diff >= 0) && (diff < WINDOW);
            sc[j] = al[j] ? sc[j] * SCALE_F : -1e30f;
            cmax = fmaxf(cmax, sc[j]);
        }
#pragma unroll
        for (int off = 4; off; off >>= 1)
            cmax = fmaxf(cmax, __shfl_xor_sync(0xffffffffu, cmax, off));

        float mnew = fmaxf(m, cmax);
        float alpha = __expf(m - mnew);   // both -1e30 -> exp(0)=1 (o,lsum are 0)

        float psum = 0.f;
#pragma unroll
        for (int j = 0; j < 4; j++) {
            float p = al[j] ? __expf(sc[j] - mnew) : 0.f;
            ps[g][l * 4 + j] = p;
            psum += p;
        }
#pragma unroll
        for (int off = 4; off; off >>= 1)
            psum += __shfl_xor_sync(0xffffffffu, psum, off);

        lsum = lsum * alpha + psum;
        m = mnew;
#pragma unroll
        for (int i = 0; i < 8; i++) o[i] *= alpha;

        __syncwarp();   // ps visibility within warp

#pragma unroll
        for (int s = 0; s < 32; s++) {
            float p = ps[g][s];
            float4 v0 = *(const float4*)&vs[s][l * 8];
            float4 v1 = *(const float4*)&vs[s][l * 8 + 4];
            o[0] += p * v0.x; o[1] += p * v0.y; o[2] += p * v0.z; o[3] += p * v0.w;
            o[4] += p * v1.x; o[5] += p * v1.y; o[6] += p * v1.z; o[7] += p * v1.w;
        }
    }

    float inv = 1.f / lsum;
    float* outp = g_att + (size_t)t * DM + h * HD + l * 8;
#pragma unroll
    for (int i = 0; i < 8; i++) outp[i] = o[i] * inv;
}

// ---------------------------------------------------------------------------
extern "C" void kernel_launch(void* const* d_in, const int* in_sizes, int n_in,
                              void* d_out, int out_size)
{
    const float* x     = (const float*)d_in[0];
    // d_in[1] tokens, d_in[2] pos: unused by the math (pos = arange)
    const float* w_qkv = (const float*)d_in[3];
    const float* w_o   = (const float*)d_in[4];
    const float* qw    = (const float*)d_in[5];
    const float* kw    = (const float*)d_in[6];
    const float* cosb  = (const float*)d_in[7];
    const float* sinb  = (const float*)d_in[8];
    float* out = (float*)d_out;

    float *qkv_p = nullptr, *att_p = nullptr;
    cudaGetSymbolAddress((void**)&qkv_p, g_qkv);
    cudaGetSymbolAddress((void**)&att_p, g_att);

    // 1) qkv = x @ w_qkv^T : [4096,3072]
    dim3 g1(3 * DM / 128, T_LEN / 128);
    gemm_nt<<<g1, 256>>>(x, w_qkv, qkv_p, T_LEN, 3 * DM, DM);

    // 2) norm + rope + v-scale
    qkv_prep<<<NH * T_LEN / 4, 128>>>(qw, kw, cosb, sinb);

    // 3) windowed attention
    dim3 ga(T_LEN / 32, NH);
    attn_kernel<<<ga, 256>>>();

    // 4) out = att @ w_o^T : [4096,1024]
    dim3 g2(DM / 128, T_LEN / 128);
    gemm_nt<<<g2, 256>>>(att_p, w_o, out, T_LEN, DM, DM);
}

// round 2
// speedup vs baseline: 2.7937x; 2.7937x over previous
#include <cuda_runtime.h>
#include <cuda_bf16.h>
#include <math.h>

#define T_LEN 4096
#define DM 1024
#define NH 16
#define HD 64
#define WINDOW 1024
#define SCALE_F 0.12f
#define EPS_F 1e-6f
#define LDP 64

// Scratch (static __device__ — no allocations allowed)
__device__ float g_qkv[(size_t)T_LEN * 3 * DM];
__device__ float g_q[(size_t)NH * T_LEN * HD];          // [h][t][d]
__device__ float g_kt[(size_t)NH * HD * T_LEN];         // [h][d][t]  (transposed)
__device__ float g_v[(size_t)NH * T_LEN * HD];          // [h][t][d]
__device__ float g_att[(size_t)T_LEN * DM];

// ---------------------------------------------------------------------------
// C[M,N] = A[M,K] @ B[N,K]^T, fp32, 128x128 tile, BK=8, double-buffered.
// ---------------------------------------------------------------------------
__global__ __launch_bounds__(256) void gemm_nt(const float* __restrict__ A,
                                               const float* __restrict__ B,
                                               float* __restrict__ C,
                                               int M, int N, int K)
{
    __shared__ float As[2][8][128];
    __shared__ float Bs[2][8][128];
    int tid = threadIdx.x;
    int tx = tid & 15;
    int ty = tid >> 4;
    int row0 = blockIdx.y * 128;
    int col0 = blockIdx.x * 128;

    int lr = tid >> 1;            // 0..127
    int lc = (tid & 1) * 4;       // 0 or 4
    const float* Aptr = A + (size_t)(row0 + lr) * K + lc;
    const float* Bptr = B + (size_t)(col0 + lr) * K + lc;

    float acc[8][8] = {};

    {
        float4 a4 = *(const float4*)Aptr;
        float4 b4 = *(const float4*)Bptr;
        As[0][lc + 0][lr] = a4.x; As[0][lc + 1][lr] = a4.y;
        As[0][lc + 2][lr] = a4.z; As[0][lc + 3][lr] = a4.w;
        Bs[0][lc + 0][lr] = b4.x; Bs[0][lc + 1][lr] = b4.y;
        Bs[0][lc + 2][lr] = b4.z; Bs[0][lc + 3][lr] = b4.w;
    }
    __syncthreads();

    int buf = 0;
    for (int k0 = 0; k0 < K; k0 += 8) {
        float4 a4, b4;
        bool more = (k0 + 8) < K;
        if (more) {
            a4 = *(const float4*)(Aptr + k0 + 8);
            b4 = *(const float4*)(Bptr + k0 + 8);
        }
#pragma unroll
        for (int kk = 0; kk < 8; kk++) {
            float4 x0 = *(const float4*)&As[buf][kk][ty * 8];
            float4 x1 = *(const float4*)&As[buf][kk][ty * 8 + 4];
            float4 y0 = *(const float4*)&Bs[buf][kk][tx * 8];
            float4 y1 = *(const float4*)&Bs[buf][kk][tx * 8 + 4];
            float a[8] = {x0.x, x0.y, x0.z, x0.w, x1.x, x1.y, x1.z, x1.w};
            float b[8] = {y0.x, y0.y, y0.z, y0.w, y1.x, y1.y, y1.z, y1.w};
#pragma unroll
            for (int i = 0; i < 8; i++)
#pragma unroll
                for (int j = 0; j < 8; j++) acc[i][j] += a[i] * b[j];
        }
        if (more) {
            As[buf ^ 1][lc + 0][lr] = a4.x; As[buf ^ 1][lc + 1][lr] = a4.y;
            As[buf ^ 1][lc + 2][lr] = a4.z; As[buf ^ 1][lc + 3][lr] = a4.w;
            Bs[buf ^ 1][lc + 0][lr] = b4.x; Bs[buf ^ 1][lc + 1][lr] = b4.y;
            Bs[buf ^ 1][lc + 2][lr] = b4.z; Bs[buf ^ 1][lc + 3][lr] = b4.w;
            __syncthreads();
            buf ^= 1;
        }
    }
#pragma unroll
    for (int i = 0; i < 8; i++) {
        size_t ro = (size_t)(row0 + ty * 8 + i) * N + col0 + tx * 8;
#pragma unroll
        for (int j = 0; j < 8; j++) C[ro + j] = acc[i][j];
    }
}

// ---------------------------------------------------------------------------
// Per (head, token): RMSNorm q,k; RoPE first 32 dims; v *= 0.5.
// q, v stored row-major; k stored transposed [h][d][t].
// ---------------------------------------------------------------------------
__global__ __launch_bounds__(128) void qkv_prep(const float* __restrict__ qw,
                                                const float* __restrict__ kw,
                                                const float* __restrict__ cosb,
                                                const float* __restrict__ sinb)
{
    int warp = threadIdx.x >> 5;
    int lane = threadIdx.x & 31;
    int idx = blockIdx.x * 4 + warp;
    int h = idx >> 12;
    int t = idx & 4095;

    const float* rowbase = g_qkv + (size_t)t * (3 * DM) + h * HD;
    float2 qv = ((const float2*)rowbase)[lane];
    float2 kv = ((const float2*)(rowbase + DM))[lane];
    float2 vv = ((const float2*)(rowbase + 2 * DM))[lane];

    float sq = qv.x * qv.x + qv.y * qv.y;
    float sk = kv.x * kv.x + kv.y * kv.y;
#pragma unroll
    for (int off = 16; off; off >>= 1) {
        sq += __shfl_xor_sync(0xffffffffu, sq, off);
        sk += __shfl_xor_sync(0xffffffffu, sk, off);
    }
    float rq = rsqrtf(sq * (1.f / 64.f) + EPS_F);
    float rk = rsqrtf(sk * (1.f / 64.f) + EPS_F);

    int d0 = lane * 2;
    float q0 = qv.x * rq * qw[d0], q1 = qv.y * rq * qw[d0 + 1];
    float k0 = kv.x * rk * kw[d0], k1 = kv.y * rk * kw[d0 + 1];

    if (lane < 16) {
        float c = cosb[t * 16 + lane];
        float s = sinb[t * 16 + lane];
        float e = q0, o = q1;
        q0 = e * c - o * s;  q1 = e * s + o * c;
        e = k0; o = k1;
        k0 = e * c - o * s;  k1 = e * s + o * c;
    }

    size_t base = ((size_t)h * T_LEN + t) * HD + d0;
    *(float2*)&g_q[base] = make_float2(q0, q1);
    *(float2*)&g_v[base] = make_float2(vv.x * 0.5f, vv.y * 0.5f);
    g_kt[((size_t)h * HD + d0) * T_LEN + t] = k0;
    g_kt[((size_t)h * HD + d0 + 1) * T_LEN + t] = k1;
}

// ---------------------------------------------------------------------------
// Sliding-window attention, 64x64 flash tiles.
// 256 threads as 16x16 grid; thread (ty,tx) owns 4 queries x 4 keys / 4 dims.
// Q and K kept d-major in smem (broadcast-friendly inner loop).
// ---------------------------------------------------------------------------
extern __shared__ float sm_attn[];

__global__ __launch_bounds__(256) void attn_kernel()
{
    float* Qst = sm_attn;                 // [d][r]  64x64
    float* Kst = sm_attn + 64 * LDP;      // [d][s]
    float* Vs  = sm_attn + 2 * 64 * LDP;  // [s][d]
    float* Ps  = sm_attn + 3 * 64 * LDP;  // [r][s]

    int h = blockIdx.y;
    int q0 = blockIdx.x * 64;
    int tid = threadIdx.x;
    int tx = tid & 15;
    int ty = tid >> 4;

    const float* qg  = g_q  + (size_t)h * T_LEN * HD;
    const float* ktg = g_kt + (size_t)h * HD * T_LEN;
    const float* vg  = g_v  + (size_t)h * T_LEN * HD;

    // load + transpose + prescale Q
#pragma unroll
    for (int it = 0; it < 4; it++) {
        int idx = tid + it * 256;
        int r = idx & 63, d4 = idx >> 6;
        float4 v = *(const float4*)&qg[(size_t)(q0 + r) * HD + d4 * 4];
        Qst[(d4 * 4 + 0) * LDP + r] = v.x * SCALE_F;
        Qst[(d4 * 4 + 1) * LDP + r] = v.y * SCALE_F;
        Qst[(d4 * 4 + 2) * LDP + r] = v.z * SCALE_F;
        Qst[(d4 * 4 + 3) * LDP + r] = v.w * SCALE_F;
    }

    float m[4], l[4], o[4][4];
#pragma unroll
    for (int i = 0; i < 4; i++) {
        m[i] = -1e30f; l[i] = 0.f;
#pragma unroll
        for (int j = 0; j < 4; j++) o[i][j] = 0.f;
    }

    int s_begin = (q0 >= WINDOW) ? q0 - WINDOW : 0;

    for (int s0 = s_begin; s0 <= q0; s0 += 64) {
        __syncthreads();
#pragma unroll
        for (int it = 0; it < 4; it++) {
            int idx = tid + it * 256;
            int c4 = (idx & 15) * 4, rr = idx >> 4;
            *(float4*)&Kst[rr * LDP + c4] = *(const float4*)&ktg[(size_t)rr * T_LEN + s0 + c4];
            *(float4*)&Vs[rr * LDP + c4]  = *(const float4*)&vg[(size_t)(s0 + rr) * HD + c4];
        }
        __syncthreads();

        float sc[4][4] = {};
#pragma unroll 16
        for (int d = 0; d < 64; d++) {
            float4 qv = *(const float4*)&Qst[d * LDP + ty * 4];
            float4 kv = *(const float4*)&Kst[d * LDP + tx * 4];
            float a[4] = {qv.x, qv.y, qv.z, qv.w};
            float b[4] = {kv.x, kv.y, kv.z, kv.w};
#pragma unroll
            for (int i = 0; i < 4; i++)
#pragma unroll
                for (int j = 0; j < 4; j++) sc[i][j] += a[i] * b[j];
        }

        bool diag = (s0 == q0);
        bool winm = (s0 == q0 - WINDOW);
        if (diag) {
#pragma unroll
            for (int i = 0; i < 4; i++)
#pragma unroll
                for (int j = 0; j < 4; j++)
                    if (tx * 4 + j > ty * 4 + i) sc[i][j] = -1e30f;
        } else if (winm) {
#pragma unroll
            for (int i = 0; i < 4; i++)
#pragma unroll
                for (int j = 0; j < 4; j++)
                    if (ty * 4 + i >= tx * 4 + j) sc[i][j] = -1e30f;
        }

#pragma unroll
        for (int i = 0; i < 4; i++) {
            float rm = fmaxf(fmaxf(sc[i][0], sc[i][1]), fmaxf(sc[i][2], sc[i][3]));
#pragma unroll
            for (int off = 8; off; off >>= 1)
                rm = fmaxf(rm, __shfl_xor_sync(0xffffffffu, rm, off));
            float mn = fmaxf(m[i], rm);
            float alpha = __expf(m[i] - mn);
            m[i] = mn;
            float ps = 0.f;
#pragma unroll
            for (int j = 0; j < 4; j++) {
                float p = (sc[i][j] > -1e29f) ? __expf(sc[i][j] - mn) : 0.f;
                sc[i][j] = p;
                ps += p;
            }
#pragma unroll
            for (int off = 8; off; off >>= 1)
                ps += __shfl_xor_sync(0xffffffffu, ps, off);
            l[i] = l[i] * alpha + ps;
#pragma unroll
            for (int j = 0; j < 4; j++) o[i][j] *= alpha;
            *(float4*)&Ps[(ty * 4 + i) * LDP + tx * 4] =
                make_float4(sc[i][0], sc[i][1], sc[i][2], sc[i][3]);
        }
        __syncthreads();

#pragma unroll 8
        for (int s = 0; s < 64; s++) {
            float4 v4 = *(const float4*)&Vs[s * LDP + tx * 4];
#pragma unroll
            for (int i = 0; i < 4; i++) {
                float p = Ps[(ty * 4 + i) * LDP + s];
                o[i][0] += p * v4.x;
                o[i][1] += p * v4.y;
                o[i][2] += p * v4.z;
                o[i][3] += p * v4.w;
            }
        }
    }

#pragma unroll
    for (int i = 0; i < 4; i++) {
        float inv = 1.f / l[i];
        float4 r = make_float4(o[i][0] * inv, o[i][1] * inv, o[i][2] * inv, o[i][3] * inv);
        *(float4*)&g_att[(size_t)(q0 + ty * 4 + i) * DM + h * HD + tx * 4] = r;
    }
}

// ---------------------------------------------------------------------------
extern "C" void kernel_launch(void* const* d_in, const int* in_sizes, int n_in,
                              void* d_out, int out_size)
{
    const float* x     = (const float*)d_in[0];
    const float* w_qkv = (const float*)d_in[3];
    const float* w_o   = (const float*)d_in[4];
    const float* qw    = (const float*)d_in[5];
    const float* kw    = (const float*)d_in[6];
    const float* cosb  = (const float*)d_in[7];
    const float* sinb  = (const float*)d_in[8];
    float* out = (float*)d_out;

    float *qkv_p = nullptr, *att_p = nullptr;
    cudaGetSymbolAddress((void**)&qkv_p, g_qkv);
    cudaGetSymbolAddress((void**)&att_p, g_att);

    // 1) qkv = x @ w_qkv^T
    dim3 g1(3 * DM / 128, T_LEN / 128);
    gemm_nt<<<g1, 256>>>(x, w_qkv, qkv_p, T_LEN, 3 * DM, DM);

    // 2) norm + rope + v-scale (+ K transpose)
    qkv_prep<<<NH * T_LEN / 4, 128>>>(qw, kw, cosb, sinb);

    // 3) windowed attention (64 KB dynamic smem)
    static bool attr_done = false;
    if (!attr_done) {
        cudaFuncSetAttribute(attn_kernel, cudaFuncAttributeMaxDynamicSharedMemorySize, 65536);
        attr_done = true;
    }
    dim3 ga(T_LEN / 64, NH);
    attn_kernel<<<ga, 256, 65536>>>();

    // 4) out = att @ w_o^T
    dim3 g2(DM / 128, T_LEN / 128);
    gemm_nt<<<g2, 256>>>(att_p, w_o, out, T_LEN, DM, DM);
}

// round 6
// speedup vs baseline: 4.4916x; 1.6078x over previous
#include <cuda_runtime.h>
#include <cuda_bf16.h>
#include <math.h>
#include <stdint.h>

#define T_LEN 4096
#define DM 1024
#define NH 16
#define HD 64
#define WINDOW 1024
#define SCALE_F 0.12f
#define EPS_F 1e-6f
#define LDP 64

// GEMM tiling
#define BM 128
#define BN 128
#define BK 32
#define SA 40            // padded smem row stride in bf16 elems (80 B)
#define STAGE_B 40960    // bytes per stage: 4 arrays * 128 * 80
#define ARR_B 10240      // bytes per 128x32 bf16 array (with pad)

// ------------------------- scratch (no allocs allowed) ----------------------
__device__ float g_qkv[(size_t)T_LEN * 3 * DM];
__device__ float g_q[(size_t)NH * T_LEN * HD];
__device__ float g_kt[(size_t)NH * HD * T_LEN];
__device__ float g_v[(size_t)NH * T_LEN * HD];
__device__ __nv_bfloat16 g_x_hi[(size_t)T_LEN * DM];
__device__ __nv_bfloat16 g_x_lo[(size_t)T_LEN * DM];
__device__ __nv_bfloat16 g_wqkv_hi[(size_t)3 * DM * DM];
__device__ __nv_bfloat16 g_wqkv_lo[(size_t)3 * DM * DM];
__device__ __nv_bfloat16 g_wo_hi[(size_t)DM * DM];
__device__ __nv_bfloat16 g_wo_lo[(size_t)DM * DM];
__device__ __nv_bfloat16 g_att_hi[(size_t)T_LEN * DM];
__device__ __nv_bfloat16 g_att_lo[(size_t)T_LEN * DM];

// ------------------------- helpers ------------------------------------------
__device__ __forceinline__ uint32_t s2u(const void* p) {
    uint32_t a;
    asm("{ .reg .u64 t; cvta.to.shared.u64 t, %1; cvt.u32.u64 %0, t; }"
        : "=r"(a) : "l"(p));
    return a;
}
__device__ __forceinline__ void cpa16(uint32_t dst, const void* src) {
    asm volatile("cp.async.cg.shared.global [%0], [%1], 16;" :: "r"(dst), "l"(src));
}
__device__ __forceinline__ void ldsm_x4(uint32_t& r0, uint32_t& r1,
                                        uint32_t& r2, uint32_t& r3, uint32_t a) {
    asm volatile("ldmatrix.sync.aligned.m8n8.x4.shared.b16 {%0,%1,%2,%3}, [%4];"
                 : "=r"(r0), "=r"(r1), "=r"(r2), "=r"(r3) : "r"(a));
}
__device__ __forceinline__ void mma16816(float* c, uint32_t a0, uint32_t a1,
                                         uint32_t a2, uint32_t a3,
                                         uint32_t b0, uint32_t b1) {
    asm volatile(
        "mma.sync.aligned.m16n8k16.row.col.f32.bf16.bf16.f32 "
        "{%0,%1,%2,%3}, {%4,%5,%6,%7}, {%8,%9}, {%0,%1,%2,%3};"
        : "+f"(c[0]), "+f"(c[1]), "+f"(c[2]), "+f"(c[3])
        : "r"(a0), "r"(a1), "r"(a2), "r"(a3), "r"(b0), "r"(b1));
}

// ---------------------------------------------------------------------------
// fp32 -> (bf16 hi, bf16 lo) split
// ---------------------------------------------------------------------------
__global__ __launch_bounds__(256) void cvt_hilo(const float* __restrict__ in,
                                                __nv_bfloat16* __restrict__ hi,
                                                __nv_bfloat16* __restrict__ lo,
                                                int n4)
{
    int i = blockIdx.x * 256 + threadIdx.x;
    if (i >= n4) return;
    float4 v = ((const float4*)in)[i];
    __nv_bfloat16 h0 = __float2bfloat16(v.x), h1 = __float2bfloat16(v.y);
    __nv_bfloat16 h2 = __float2bfloat16(v.z), h3 = __float2bfloat16(v.w);
    __nv_bfloat16 l0 = __float2bfloat16(v.x - __bfloat162float(h0));
    __nv_bfloat16 l1 = __float2bfloat16(v.y - __bfloat162float(h1));
    __nv_bfloat16 l2 = __float2bfloat16(v.z - __bfloat162float(h2));
    __nv_bfloat16 l3 = __float2bfloat16(v.w - __bfloat162float(h3));
    ((__nv_bfloat162*)hi)[2 * i]     = __halves2bfloat162(h0, h1);
    ((__nv_bfloat162*)hi)[2 * i + 1] = __halves2bfloat162(h2, h3);
    ((__nv_bfloat162*)lo)[2 * i]     = __halves2bfloat162(l0, l1);
    ((__nv_bfloat162*)lo)[2 * i + 1] = __halves2bfloat162(l2, l3);
}

// ---------------------------------------------------------------------------
// mma.sync GEMM: C[M,N] = A@B^T, fp32-equivalent via bf16 3-term split.
// 128x128 tile, BK=32, 8 warps (2x4), 64x32 warp tile, double-buffered cp.async.
// ---------------------------------------------------------------------------
extern __shared__ __align__(128) char gsm[];

__global__ __launch_bounds__(256, 1) void gemm_mma(const __nv_bfloat16* __restrict__ Ahi,
                                                   const __nv_bfloat16* __restrict__ Alo,
                                                   const __nv_bfloat16* __restrict__ Bhi,
                                                   const __nv_bfloat16* __restrict__ Blo,
                                                   float* __restrict__ C,
                                                   int M, int N, int K)
{
    uint32_t sbase = s2u(gsm);
    int tid = threadIdx.x;
    int wid = tid >> 5;
    int lane = tid & 31;
    int wm = (wid >> 2) * 64;
    int wn = (wid & 3) * 32;
    int row0 = blockIdx.y * BM;
    int col0 = blockIdx.x * BN;

    // ---- cp.async source pointers (per thread: 2 rows per array) ----
    int lrow = tid >> 2;            // 0..63
    int lkc = tid & 3;              // 16B chunk within 64B row
    const char* gAh = (const char*)(Ahi + (size_t)(row0 + lrow) * K + lkc * 8);
    const char* gAl = (const char*)(Alo + (size_t)(row0 + lrow) * K + lkc * 8);
    const char* gBh = (const char*)(Bhi + (size_t)(col0 + lrow) * K + lkc * 8);
    const char* gBl = (const char*)(Blo + (size_t)(col0 + lrow) * K + lkc * 8);
    size_t gstep = (size_t)64 * K * 2;     // +64 rows
    uint32_t soff0 = lrow * 80 + lkc * 16;
    uint32_t soff1 = soff0 + 64 * 80;

#define LOAD_STAGE(st, k0)                                                  \
    do {                                                                    \
        uint32_t sb = sbase + (st) * STAGE_B;                               \
        size_t go = (size_t)(k0) * 2;                                       \
        cpa16(sb + soff0,             gAh + go);                            \
        cpa16(sb + soff1,             gAh + go + gstep);                    \
        cpa16(sb + ARR_B + soff0,     gAl + go);                            \
        cpa16(sb + ARR_B + soff1,     gAl + go + gstep);                    \
        cpa16(sb + 2 * ARR_B + soff0, gBh + go);                            \
        cpa16(sb + 2 * ARR_B + soff1, gBh + go + gstep);                    \
        cpa16(sb + 3 * ARR_B + soff0, gBl + go);                            \
        cpa16(sb + 3 * ARR_B + soff1, gBl + go + gstep);                    \
    } while (0)

    float acc[4][4][4] = {};

    // ldmatrix lane->address components
    int a_r = wm + (lane & 15);                                // A row
    int a_c0 = (lane >> 4) << 3;                               // A col half
    int b_r = wn + ((lane >> 4) << 3) + (lane & 7);            // B row (n)
    int b_c0 = ((lane >> 3) & 1) << 3;                         // B col half

    LOAD_STAGE(0, 0);
    asm volatile("cp.async.commit_group;" ::: "memory");

    const int NKT = K / BK;
    for (int kt = 0; kt < NKT; kt++) {
        if (kt + 1 < NKT) {
            LOAD_STAGE((kt + 1) & 1, (kt + 1) * BK);
            asm volatile("cp.async.commit_group;" ::: "memory");
            asm volatile("cp.async.wait_group 1;" ::: "memory");
        } else {
            asm volatile("cp.async.commit_group;" ::: "memory");
            asm volatile("cp.async.wait_group 0;" ::: "memory");
        }
        __syncthreads();

        uint32_t stb = sbase + (kt & 1) * STAGE_B;
#pragma unroll
        for (int ks = 0; ks < 2; ks++) {
            uint32_t ah[4][4], al[4][4];
            int acol = ks * 16 + a_c0;
#pragma unroll
            for (int mt = 0; mt < 4; mt++) {
                uint32_t aaddr = stb + ((a_r + mt * 16) * SA + acol) * 2;
                ldsm_x4(ah[mt][0], ah[mt][1], ah[mt][2], ah[mt][3], aaddr);
                ldsm_x4(al[mt][0], al[mt][1], al[mt][2], al[mt][3], aaddr + ARR_B);
            }
            int bcol = ks * 16 + b_c0;
#pragma unroll
            for (int nt2 = 0; nt2 < 2; nt2++) {
                uint32_t bh0, bh1, bh2, bh3, bl0, bl1, bl2, bl3;
                uint32_t baddr = stb + 2 * ARR_B + ((b_r + nt2 * 16) * SA + bcol) * 2;
                ldsm_x4(bh0, bh1, bh2, bh3, baddr);
                ldsm_x4(bl0, bl1, bl2, bl3, baddr + ARR_B);
#pragma unroll
                for (int mt = 0; mt < 4; mt++) {
                    mma16816(acc[mt][2 * nt2], ah[mt][0], ah[mt][1], ah[mt][2], ah[mt][3], bh0, bh1);
                    mma16816(acc[mt][2 * nt2], ah[mt][0], ah[mt][1], ah[mt][2], ah[mt][3], bl0, bl1);
                    mma16816(acc[mt][2 * nt2], al[mt][0], al[mt][1], al[mt][2], al[mt][3], bh0, bh1);
                    mma16816(acc[mt][2 * nt2 + 1], ah[mt][0], ah[mt][1], ah[mt][2], ah[mt][3], bh2, bh3);
                    mma16816(acc[mt][2 * nt2 + 1], ah[mt][0], ah[mt][1], ah[mt][2], ah[mt][3], bl2, bl3);
                    mma16816(acc[mt][2 * nt2 + 1], al[mt][0], al[mt][1], al[mt][2], al[mt][3], bh2, bh3);
                }
            }
        }
        __syncthreads();
    }
#undef LOAD_STAGE

    // epilogue
    int erow = row0 + wm + (lane >> 2);
    int ecol0 = col0 + wn + (lane & 3) * 2;
#pragma unroll
    for (int mt = 0; mt < 4; mt++) {
#pragma unroll
        for (int nt = 0; nt < 4; nt++) {
            float* c = acc[mt][nt];
            size_t r0i = (size_t)(erow + mt * 16) * N + ecol0 + nt * 8;
            *(float2*)&C[r0i]            = make_float2(c[0], c[1]);
            *(float2*)&C[r0i + 8 * N]    = make_float2(c[2], c[3]);
        }
    }
}

// ---------------------------------------------------------------------------
// Per (head, token): RMSNorm q,k; RoPE first 32 dims; v *= 0.5.
// ---------------------------------------------------------------------------
__global__ __launch_bounds__(128) void qkv_prep(const float* __restrict__ qw,
                                                const float* __restrict__ kw,
                                                const float* __restrict__ cosb,
                                                const float* __restrict__ sinb)
{
    int warp = threadIdx.x >> 5;
    int lane = threadIdx.x & 31;
    int idx = blockIdx.x * 4 + warp;
    int h = idx >> 12;
    int t = idx & 4095;

    const float* rowbase = g_qkv + (size_t)t * (3 * DM) + h * HD;
    float2 qv = ((const float2*)rowbase)[lane];
    float2 kv = ((const float2*)(rowbase + DM))[lane];
    float2 vv = ((const float2*)(rowbase + 2 * DM))[lane];

    float sq = qv.x * qv.x + qv.y * qv.y;
    float sk = kv.x * kv.x + kv.y * kv.y;
#pragma unroll
    for (int off = 16; off; off >>= 1) {
        sq += __shfl_xor_sync(0xffffffffu, sq, off);
        sk += __shfl_xor_sync(0xffffffffu, sk, off);
    }
    float rq = rsqrtf(sq * (1.f / 64.f) + EPS_F);
    float rk = rsqrtf(sk * (1.f / 64.f) + EPS_F);

    int d0 = lane * 2;
    float q0 = qv.x * rq * qw[d0], q1 = qv.y * rq * qw[d0 + 1];
    float k0 = kv.x * rk * kw[d0], k1 = kv.y * rk * kw[d0 + 1];

    if (lane < 16) {
        float c = cosb[t * 16 + lane];
        float s = sinb[t * 16 + lane];
        float e = q0, o = q1;
        q0 = e * c - o * s;  q1 = e * s + o * c;
        e = k0; o = k1;
        k0 = e * c - o * s;  k1 = e * s + o * c;
    }

    size_t base = ((size_t)h * T_LEN + t) * HD + d0;
    *(float2*)&g_q[base] = make_float2(q0, q1);
    *(float2*)&g_v[base] = make_float2(vv.x * 0.5f, vv.y * 0.5f);
    g_kt[((size_t)h * HD + d0) * T_LEN + t] = k0;
    g_kt[((size_t)h * HD + d0 + 1) * T_LEN + t] = k1;
}

// ---------------------------------------------------------------------------
// Sliding-window attention, 64x64 flash tiles (fp32), epilogue -> bf16 hi/lo.
// ---------------------------------------------------------------------------
extern __shared__ float sm_attn[];

__global__ __launch_bounds__(256) void attn_kernel()
{
    float* Qst = sm_attn;
    float* Kst = sm_attn + 64 * LDP;
    float* Vs  = sm_attn + 2 * 64 * LDP;
    float* Ps  = sm_attn + 3 * 64 * LDP;

    int h = blockIdx.y;
    int q0 = blockIdx.x * 64;
    int tid = threadIdx.x;
    int tx = tid & 15;
    int ty = tid >> 4;

    const float* qg  = g_q  + (size_t)h * T_LEN * HD;
    const float* ktg = g_kt + (size_t)h * HD * T_LEN;
    const float* vg  = g_v  + (size_t)h * T_LEN * HD;

#pragma unroll
    for (int it = 0; it < 4; it++) {
        int idx = tid + it * 256;
        int r = idx & 63, d4 = idx >> 6;
        float4 v = *(const float4*)&qg[(size_t)(q0 + r) * HD + d4 * 4];
        Qst[(d4 * 4 + 0) * LDP + r] = v.x * SCALE_F;
        Qst[(d4 * 4 + 1) * LDP + r] = v.y * SCALE_F;
        Qst[(d4 * 4 + 2) * LDP + r] = v.z * SCALE_F;
        Qst[(d4 * 4 + 3) * LDP + r] = v.w * SCALE_F;
    }

    float m[4], l[4], o[4][4];
#pragma unroll
    for (int i = 0; i < 4; i++) {
        m[i] = -1e30f; l[i] = 0.f;
#pragma unroll
        for (int j = 0; j < 4; j++) o[i][j] = 0.f;
    }

    int s_begin = (q0 >= WINDOW) ? q0 - WINDOW : 0;

    for (int s0 = s_begin; s0 <= q0; s0 += 64) {
        __syncthreads();
#pragma unroll
        for (int it = 0; it < 4; it++) {
            int idx = tid + it * 256;
            int c4 = (idx & 15) * 4, rr = idx >> 4;
            *(float4*)&Kst[rr * LDP + c4] = *(const float4*)&ktg[(size_t)rr * T_LEN + s0 + c4];
            *(float4*)&Vs[rr * LDP + c4]  = *(const float4*)&vg[(size_t)(s0 + rr) * HD + c4];
        }
        __syncthreads();

        float sc[4][4] = {};
#pragma unroll 16
        for (int d = 0; d < 64; d++) {
            float4 qv = *(const float4*)&Qst[d * LDP + ty * 4];
            float4 kv = *(const float4*)&Kst[d * LDP + tx * 4];
            float a[4] = {qv.x, qv.y, qv.z, qv.w};
            float b[4] = {kv.x, kv.y, kv.z, kv.w};
#pragma unroll
            for (int i = 0; i < 4; i++)
#pragma unroll
                for (int j = 0; j < 4; j++) sc[i][j] += a[i] * b[j];
        }

        bool diag = (s0 == q0);
        bool winm = (s0 == q0 - WINDOW);
        if (diag) {
#pragma unroll
            for (int i = 0; i < 4; i++)
#pragma unroll
                for (int j = 0; j < 4; j++)
                    if (tx * 4 + j > ty * 4 + i) sc[i][j] = -1e30f;
        } else if (winm) {
#pragma unroll
            for (int i = 0; i < 4; i++)
#pragma unroll
                for (int j = 0; j < 4; j++)
                    if (ty * 4 + i >= tx * 4 + j) sc[i][j] = -1e30f;
        }

#pragma unroll
        for (int i = 0; i < 4; i++) {
            float rm = fmaxf(fmaxf(sc[i][0], sc[i][1]), fmaxf(sc[i][2], sc[i][3]));
#pragma unroll
            for (int off = 8; off; off >>= 1)
                rm = fmaxf(rm, __shfl_xor_sync(0xffffffffu, rm, off));
            float mn = fmaxf(m[i], rm);
            float alpha = __expf(m[i] - mn);
            m[i] = mn;
            float ps = 0.f;
#pragma unroll
            for (int j = 0; j < 4; j++) {
                float p = (sc[i][j] > -1e29f) ? __expf(sc[i][j] - mn) : 0.f;
                sc[i][j] = p;
                ps += p;
            }
#pragma unroll
            for (int off = 8; off; off >>= 1)
                ps += __shfl_xor_sync(0xffffffffu, ps, off);
            l[i] = l[i] * alpha + ps;
#pragma unroll
            for (int j = 0; j < 4; j++) o[i][j] *= alpha;
            *(float4*)&Ps[(ty * 4 + i) * LDP + tx * 4] =
                make_float4(sc[i][0], sc[i][1], sc[i][2], sc[i][3]);
        }
        __syncthreads();

#pragma unroll 8
        for (int s = 0; s < 64; s++) {
            float4 v4 = *(const float4*)&Vs[s * LDP + tx * 4];
#pragma unroll
            for (int i = 0; i < 4; i++) {
                float p = Ps[(ty * 4 + i) * LDP + s];
                o[i][0] += p * v4.x;
                o[i][1] += p * v4.y;
                o[i][2] += p * v4.z;
                o[i][3] += p * v4.w;
            }
        }
    }

#pragma unroll
    for (int i = 0; i < 4; i++) {
        float inv = 1.f / l[i];
        float v0 = o[i][0] * inv, v1 = o[i][1] * inv;
        float v2 = o[i][2] * inv, v3 = o[i][3] * inv;
        size_t base = (size_t)(q0 + ty * 4 + i) * DM + h * HD + tx * 4;
        __nv_bfloat16 h0 = __float2bfloat16(v0), h1 = __float2bfloat16(v1);
        __nv_bfloat16 h2 = __float2bfloat16(v2), h3 = __float2bfloat16(v3);
        *(__nv_bfloat162*)&g_att_hi[base]     = __halves2bfloat162(h0, h1);
        *(__nv_bfloat162*)&g_att_hi[base + 2] = __halves2bfloat162(h2, h3);
        __nv_bfloat16 l0 = __float2bfloat16(v0 - __bfloat162float(h0));
        __nv_bfloat16 l1 = __float2bfloat16(v1 - __bfloat162float(h1));
        __nv_bfloat16 l2 = __float2bfloat16(v2 - __bfloat162float(h2));
        __nv_bfloat16 l3 = __float2bfloat16(v3 - __bfloat162float(h3));
        *(__nv_bfloat162*)&g_att_lo[base]     = __halves2bfloat162(l0, l1);
        *(__nv_bfloat162*)&g_att_lo[base + 2] = __halves2bfloat162(l2, l3);
    }
}

// ---------------------------------------------------------------------------
extern "C" void kernel_launch(void* const* d_in, const int* in_sizes, int n_in,
                              void* d_out, int out_size)
{
    const float* x     = (const float*)d_in[0];
    const float* w_qkv = (const float*)d_in[3];
    const float* w_o   = (const float*)d_in[4];
    const float* qw    = (const float*)d_in[5];
    const float* kw    = (const float*)d_in[6];
    const float* cosb  = (const float*)d_in[7];
    const float* sinb  = (const float*)d_in[8];
    float* out = (float*)d_out;

    float* qkv_p = nullptr;
    __nv_bfloat16 *xh, *xl, *wqh, *wql, *woh, *wol, *ath, *atl;
    cudaGetSymbolAddress((void**)&qkv_p, g_qkv);
    cudaGetSymbolAddress((void**)&xh, g_x_hi);
    cudaGetSymbolAddress((void**)&xl, g_x_lo);
    cudaGetSymbolAddress((void**)&wqh, g_wqkv_hi);
    cudaGetSymbolAddress((void**)&wql, g_wqkv_lo);
    cudaGetSymbolAddress((void**)&woh, g_wo_hi);
    cudaGetSymbolAddress((void**)&wol, g_wo_lo);
    cudaGetSymbolAddress((void**)&ath, g_att_hi);
    cudaGetSymbolAddress((void**)&atl, g_att_lo);

    static bool attr_done = false;
    if (!attr_done) {
        cudaFuncSetAttribute(attn_kernel, cudaFuncAttributeMaxDynamicSharedMemorySize, 65536);
        cudaFuncSetAttribute(gemm_mma, cudaFuncAttributeMaxDynamicSharedMemorySize, 2 * STAGE_B);
        attr_done = true;
    }

    // 0) split inputs to bf16 hi/lo
    cvt_hilo<<<(T_LEN * DM / 4 + 255) / 256, 256>>>(x, xh, xl, T_LEN * DM / 4);
    cvt_hilo<<<(3 * DM * DM / 4 + 255) / 256, 256>>>(w_qkv, wqh, wql, 3 * DM * DM / 4);
    cvt_hilo<<<(DM * DM / 4 + 255) / 256, 256>>>(w_o, woh, wol, DM * DM / 4);

    // 1) qkv = x @ w_qkv^T  (tensor cores via mma.sync)
    dim3 g1(3 * DM / BN, T_LEN / BM);
    gemm_mma<<<g1, 256, 2 * STAGE_B>>>(xh, xl, wqh, wql, qkv_p, T_LEN, 3 * DM, DM);

    // 2) norm + rope + v-scale (+ K transpose)
    qkv_prep<<<NH * T_LEN / 4, 128>>>(qw, kw, cosb, sinb);

    // 3) windowed attention -> att (bf16 hi/lo)
    dim3 ga(T_LEN / 64, NH);
    attn_kernel<<<ga, 256, 65536>>>();

    // 4) out = att @ w_o^T  (tensor cores via mma.sync)
    dim3 g2(DM / BN, T_LEN / BM);
    gemm_mma<<<g2, 256, 2 * STAGE_B>>>(ath, atl, woh, wol, out, T_LEN, DM, DM);
}

// round 9
// speedup vs baseline: 6.4239x; 1.4302x over previous
#include <cuda_runtime.h>
#include <cuda_bf16.h>
#include <math.h>
#include <stdint.h>

#define T_LEN 4096
#define DM 1024
#define NH 16
#define HD 64
#define WINDOW 1024
#define EPS_F 1e-6f
#define QSC 0.17312340490667564f   // 0.12 * log2(e)

// GEMM tiling
#define BM 128
#define BN 128
#define BK 32
#define SA 40
#define STAGE_B 40960
#define ARR_B 10240

// Attention smem geometry
#define AST 72                      // padded row stride (bf16 elems), 144 B
#define Q_BYTES 18432               // 128 * 144
#define KV_ARR 9216                 // 64 * 144
#define KV_STAGE 36864              // 4 arrays
#define ATTN_SMEM (2 * Q_BYTES + 2 * KV_STAGE)   // 110592

// ------------------------- scratch (no allocs allowed) ----------------------
__device__ float g_qkv[(size_t)T_LEN * 3 * DM];
__device__ __nv_bfloat16 g_x_hi[(size_t)T_LEN * DM];
__device__ __nv_bfloat16 g_x_lo[(size_t)T_LEN * DM];
__device__ __nv_bfloat16 g_wqkv_hi[(size_t)3 * DM * DM];
__device__ __nv_bfloat16 g_wqkv_lo[(size_t)3 * DM * DM];
__device__ __nv_bfloat16 g_wo_hi[(size_t)DM * DM];
__device__ __nv_bfloat16 g_wo_lo[(size_t)DM * DM];
__device__ __nv_bfloat16 g_att_hi[(size_t)T_LEN * DM];
__device__ __nv_bfloat16 g_att_lo[(size_t)T_LEN * DM];
__device__ __nv_bfloat16 g_qs_hi[(size_t)NH * T_LEN * HD];   // [h][t][d], pre-scaled
__device__ __nv_bfloat16 g_qs_lo[(size_t)NH * T_LEN * HD];
__device__ __nv_bfloat16 g_ks_hi[(size_t)NH * T_LEN * HD];   // [h][t][d]
__device__ __nv_bfloat16 g_ks_lo[(size_t)NH * T_LEN * HD];
__device__ __nv_bfloat16 g_vt_hi[(size_t)NH * HD * T_LEN];   // [h][d][t], v*0.5
__device__ __nv_bfloat16 g_vt_lo[(size_t)NH * HD * T_LEN];

// ------------------------- helpers ------------------------------------------
__device__ __forceinline__ uint32_t s2u(const void* p) {
    uint32_t a;
    asm("{ .reg .u64 t; cvta.to.shared.u64 t, %1; cvt.u32.u64 %0, t; }"
        : "=r"(a) : "l"(p));
    return a;
}
__device__ __forceinline__ void cpa16(uint32_t dst, const void* src) {
    asm volatile("cp.async.cg.shared.global [%0], [%1], 16;" :: "r"(dst), "l"(src));
}
__device__ __forceinline__ void ldsm_x4(uint32_t& r0, uint32_t& r1,
                                        uint32_t& r2, uint32_t& r3, uint32_t a) {
    asm volatile("ldmatrix.sync.aligned.m8n8.x4.shared.b16 {%0,%1,%2,%3}, [%4];"
                 : "=r"(r0), "=r"(r1), "=r"(r2), "=r"(r3) : "r"(a));
}
__device__ __forceinline__ void mma16816(float* c, uint32_t a0, uint32_t a1,
                                         uint32_t a2, uint32_t a3,
                                         uint32_t b0, uint32_t b1) {
    asm volatile(
        "mma.sync.aligned.m16n8k16.row.col.f32.bf16.bf16.f32 "
        "{%0,%1,%2,%3}, {%4,%5,%6,%7}, {%8,%9}, {%0,%1,%2,%3};"
        : "+f"(c[0]), "+f"(c[1]), "+f"(c[2]), "+f"(c[3])
        : "r"(a0), "r"(a1), "r"(a2), "r"(a3), "r"(b0), "r"(b1));
}
__device__ __forceinline__ float fex2(float x) {
    float y;
    asm("ex2.approx.ftz.f32 %0, %1;" : "=f"(y) : "f"(x));
    return y;
}
__device__ __forceinline__ uint32_t packbf2(float a, float b) {
    __nv_bfloat162 p = __halves2bfloat162(__float2bfloat16(a), __float2bfloat16(b));
    return *(uint32_t*)&p;
}
__device__ __forceinline__ void packpl(float p0, float p1, uint32_t& hi, uint32_t& lo) {
    __nv_bfloat16 h0 = __float2bfloat16(p0), h1 = __float2bfloat16(p1);
    __nv_bfloat162 hp = __halves2bfloat162(h0, h1);
    hi = *(uint32_t*)&hp;
    __nv_bfloat162 lp = __halves2bfloat162(__float2bfloat16(p0 - __bfloat162float(h0)),
                                           __float2bfloat16(p1 - __bfloat162float(h1)));
    lo = *(uint32_t*)&lp;
}

// ---------------------------------------------------------------------------
// fp32 -> (bf16 hi, bf16 lo) split
// ---------------------------------------------------------------------------
__global__ __launch_bounds__(256) void cvt_hilo(const float* __restrict__ in,
                                                __nv_bfloat16* __restrict__ hi,
                                                __nv_bfloat16* __restrict__ lo,
                                                int n4)
{
    int i = blockIdx.x * 256 + threadIdx.x;
    if (i >= n4) return;
    float4 v = ((const float4*)in)[i];
    ((uint32_t*)hi)[2 * i]     = packbf2(v.x, v.y);
    ((uint32_t*)hi)[2 * i + 1] = packbf2(v.z, v.w);
    float hx = __bfloat162float(__float2bfloat16(v.x));
    float hy = __bfloat162float(__float2bfloat16(v.y));
    float hz = __bfloat162float(__float2bfloat16(v.z));
    float hw = __bfloat162float(__float2bfloat16(v.w));
    ((uint32_t*)lo)[2 * i]     = packbf2(v.x - hx, v.y - hy);
    ((uint32_t*)lo)[2 * i + 1] = packbf2(v.z - hz, v.w - hw);
}

// ---------------------------------------------------------------------------
// mma.sync GEMM (unchanged from round 6)
// ---------------------------------------------------------------------------
extern __shared__ __align__(128) char gsm[];

__global__ __launch_bounds__(256, 1) void gemm_mma(const __nv_bfloat16* __restrict__ Ahi,
                                                   const __nv_bfloat16* __restrict__ Alo,
                                                   const __nv_bfloat16* __restrict__ Bhi,
                                                   const __nv_bfloat16* __restrict__ Blo,
                                                   float* __restrict__ C,
                                                   int M, int N, int K)
{
    uint32_t sbase = s2u(gsm);
    int tid = threadIdx.x;
    int wid = tid >> 5;
    int lane = tid & 31;
    int wm = (wid >> 2) * 64;
    int wn = (wid & 3) * 32;
    int row0 = blockIdx.y * BM;
    int col0 = blockIdx.x * BN;

    int lrow = tid >> 2;
    int lkc = tid & 3;
    const char* gAh = (const char*)(Ahi + (size_t)(row0 + lrow) * K + lkc * 8);
    const char* gAl = (const char*)(Alo + (size_t)(row0 + lrow) * K + lkc * 8);
    const char* gBh = (const char*)(Bhi + (size_t)(col0 + lrow) * K + lkc * 8);
    const char* gBl = (const char*)(Blo + (size_t)(col0 + lrow) * K + lkc * 8);
    size_t gstep = (size_t)64 * K * 2;
    uint32_t soff0 = lrow * 80 + lkc * 16;
    uint32_t soff1 = soff0 + 64 * 80;

#define LOAD_STAGE(st, k0)                                                  \
    do {                                                                    \
        uint32_t sb = sbase + (st) * STAGE_B;                               \
        size_t go = (size_t)(k0) * 2;                                       \
        cpa16(sb + soff0,             gAh + go);                            \
        cpa16(sb + soff1,             gAh + go + gstep);                    \
        cpa16(sb + ARR_B + soff0,     gAl + go);                            \
        cpa16(sb + ARR_B + soff1,     gAl + go + gstep);                    \
        cpa16(sb + 2 * ARR_B + soff0, gBh + go);                            \
        cpa16(sb + 2 * ARR_B + soff1, gBh + go + gstep);                    \
        cpa16(sb + 3 * ARR_B + soff0, gBl + go);                            \
        cpa16(sb + 3 * ARR_B + soff1, gBl + go + gstep);                    \
    } while (0)

    float acc[4][4][4] = {};

    int a_r = wm + (lane & 15);
    int a_c0 = (lane >> 4) << 3;
    int b_r = wn + ((lane >> 4) << 3) + (lane & 7);
    int b_c0 = ((lane >> 3) & 1) << 3;

    LOAD_STAGE(0, 0);
    asm volatile("cp.async.commit_group;" ::: "memory");

    const int NKT = K / BK;
    for (int kt = 0; kt < NKT; kt++) {
        if (kt + 1 < NKT) {
            LOAD_STAGE((kt + 1) & 1, (kt + 1) * BK);
            asm volatile("cp.async.commit_group;" ::: "memory");
            asm volatile("cp.async.wait_group 1;" ::: "memory");
        } else {
            asm volatile("cp.async.commit_group;" ::: "memory");
            asm volatile("cp.async.wait_group 0;" ::: "memory");
        }
        __syncthreads();

        uint32_t stb = sbase + (kt & 1) * STAGE_B;
#pragma unroll
        for (int ks = 0; ks < 2; ks++) {
            uint32_t ah[4][4], al[4][4];
            int acol = ks * 16 + a_c0;
#pragma unroll
            for (int mt = 0; mt < 4; mt++) {
                uint32_t aaddr = stb + ((a_r + mt * 16) * SA + acol) * 2;
                ldsm_x4(ah[mt][0], ah[mt][1], ah[mt][2], ah[mt][3], aaddr);
                ldsm_x4(al[mt][0], al[mt][1], al[mt][2], al[mt][3], aaddr + ARR_B);
            }
            int bcol = ks * 16 + b_c0;
#pragma unroll
            for (int nt2 = 0; nt2 < 2; nt2++) {
                uint32_t bh0, bh1, bh2, bh3, bl0, bl1, bl2, bl3;
                uint32_t baddr = stb + 2 * ARR_B + ((b_r + nt2 * 16) * SA + bcol) * 2;
                ldsm_x4(bh0, bh1, bh2, bh3, baddr);
                ldsm_x4(bl0, bl1, bl2, bl3, baddr + ARR_B);
#pragma unroll
                for (int mt = 0; mt < 4; mt++) {
                    mma16816(acc[mt][2 * nt2], ah[mt][0], ah[mt][1], ah[mt][2], ah[mt][3], bh0, bh1);
                    mma16816(acc[mt][2 * nt2], ah[mt][0], ah[mt][1], ah[mt][2], ah[mt][3], bl0, bl1);
                    mma16816(acc[mt][2 * nt2], al[mt][0], al[mt][1], al[mt][2], al[mt][3], bh0, bh1);
                    mma16816(acc[mt][2 * nt2 + 1], ah[mt][0], ah[mt][1], ah[mt][2], ah[mt][3], bh2, bh3);
                    mma16816(acc[mt][2 * nt2 + 1], ah[mt][0], ah[mt][1], ah[mt][2], ah[mt][3], bl2, bl3);
                    mma16816(acc[mt][2 * nt2 + 1], al[mt][0], al[mt][1], al[mt][2], al[mt][3], bh2, bh3);
                }
            }
        }
        __syncthreads();
    }
#undef LOAD_STAGE

    int erow = row0 + wm + (lane >> 2);
    int ecol0 = col0 + wn + (lane & 3) * 2;
#pragma unroll
    for (int mt = 0; mt < 4; mt++) {
#pragma unroll
        for (int nt = 0; nt < 4; nt++) {
            float* c = acc[mt][nt];
            size_t r0i = (size_t)(erow + mt * 16) * N + ecol0 + nt * 8;
            *(float2*)&C[r0i]         = make_float2(c[0], c[1]);
            *(float2*)&C[r0i + 8 * N] = make_float2(c[2], c[3]);
        }
    }
}

// ---------------------------------------------------------------------------
// qkv_prep: RMSNorm q,k + RoPE + v*0.5, emit bf16 hi/lo:
//   q scaled by 0.12*log2e -> g_qs  [h][t][d]
//   k                      -> g_ks  [h][t][d]
//   v*0.5 transposed       -> g_vt  [h][d][t]   (smem-staged transpose)
// Block: one head x 32 tokens; warp w handles tokens w*4..w*4+3.
// ---------------------------------------------------------------------------
__global__ __launch_bounds__(256) void qkv_prep(const float* __restrict__ qw,
                                                const float* __restrict__ kw,
                                                const float* __restrict__ cosb,
                                                const float* __restrict__ sinb)
{
    __shared__ float vt_s[64][33];
    int tid = threadIdx.x;
    int wid = tid >> 5, lane = tid & 31;
    int h = blockIdx.y;
    int t0 = blockIdx.x * 32;

#pragma unroll
    for (int j = 0; j < 4; j++) {
        int tl = wid * 4 + j;
        int t = t0 + tl;
        const float* rowbase = g_qkv + (size_t)t * (3 * DM) + h * HD;
        float2 qv = ((const float2*)rowbase)[lane];
        float2 kv = ((const float2*)(rowbase + DM))[lane];
        float2 vv = ((const float2*)(rowbase + 2 * DM))[lane];

        float sq = qv.x * qv.x + qv.y * qv.y;
        float sk = kv.x * kv.x + kv.y * kv.y;
#pragma unroll
        for (int off = 16; off; off >>= 1) {
            sq += __shfl_xor_sync(0xffffffffu, sq, off);
            sk += __shfl_xor_sync(0xffffffffu, sk, off);
        }
        float rq = rsqrtf(sq * (1.f / 64.f) + EPS_F);
        float rk = rsqrtf(sk * (1.f / 64.f) + EPS_F);

        int d0 = lane * 2;
        float q0 = qv.x * rq * qw[d0], q1 = qv.y * rq * qw[d0 + 1];
        float k0 = kv.x * rk * kw[d0], k1 = kv.y * rk * kw[d0 + 1];

        if (lane < 16) {
            float c = cosb[t * 16 + lane];
            float s = sinb[t * 16 + lane];
            float e = q0, o = q1;
            q0 = e * c - o * s;  q1 = e * s + o * c;
            e = k0; o = k1;
            k0 = e * c - o * s;  k1 = e * s + o * c;
        }
        q0 *= QSC; q1 *= QSC;

        size_t base = ((size_t)h * T_LEN + t) * HD + d0;
        uint32_t ph, pl;
        packpl(q0, q1, ph, pl);
        *(uint32_t*)&g_qs_hi[base] = ph;
        *(uint32_t*)&g_qs_lo[base] = pl;
        packpl(k0, k1, ph, pl);
        *(uint32_t*)&g_ks_hi[base] = ph;
        *(uint32_t*)&g_ks_lo[base] = pl;

        vt_s[d0][tl]     = vv.x * 0.5f;
        vt_s[d0 + 1][tl] = vv.y * 0.5f;
    }
    __syncthreads();

    // cooperative transposed write: thread -> (d, 8 t values)
    int d = tid >> 2;
    int tg = (tid & 3) * 8;
    uint32_t hi[4], lo[4];
#pragma unroll
    for (int i = 0; i < 4; i++) {
        float a = vt_s[d][tg + 2 * i], b = vt_s[d][tg + 2 * i + 1];
        packpl(a, b, hi[i], lo[i]);
    }
    size_t vbase = ((size_t)h * HD + d) * T_LEN + t0 + tg;
    *(uint4*)&g_vt_hi[vbase] = make_uint4(hi[0], hi[1], hi[2], hi[3]);
    *(uint4*)&g_vt_lo[vbase] = make_uint4(lo[0], lo[1], lo[2], lo[3]);
}

// ---------------------------------------------------------------------------
// Tensor-core flash attention. CTA = 128 q-rows x 1 head, 8 warps (m16 each).
// K-chunks of 64, double-buffered cp.async. 3-term bf16 hi/lo on both GEMMs.
// Scores in log2-space (Q pre-scaled by 0.12*log2e) -> softmax uses ex2.
// SMEM: Qhi(18432) Qlo(18432) | stage{0,1}: Khi Klo Vthi Vtlo (9216 each)
// ---------------------------------------------------------------------------
__device__ __forceinline__ void attn_load_chunk(uint32_t sb0, int stage, int s0,
                                                int h, int tid)
{
    int arr = tid >> 6, r = tid & 63;
    uint32_t dst = sb0 + 2 * Q_BYTES + stage * KV_STAGE + arr * KV_ARR + r * 144;
    const __nv_bfloat16* src;
    if (arr == 0)      src = g_ks_hi + ((size_t)h * T_LEN + s0 + r) * HD;
    else if (arr == 1) src = g_ks_lo + ((size_t)h * T_LEN + s0 + r) * HD;
    else if (arr == 2) src = g_vt_hi + ((size_t)h * HD + r) * T_LEN + s0;
    else               src = g_vt_lo + ((size_t)h * HD + r) * T_LEN + s0;
#pragma unroll
    for (int c = 0; c < 8; c++) cpa16(dst + c * 16, (const char*)src + c * 16);
}

__global__ __launch_bounds__(256, 1) void attn_mma()
{
    uint32_t sb0 = s2u(gsm);
    int tid = threadIdx.x;
    int wid = tid >> 5, lane = tid & 31;
    int h = blockIdx.y;
    int q0 = blockIdx.x * 128;

    // Q loads (both hi/lo arrays)
    {
        int arr = tid >> 7, r = tid & 127;
        const __nv_bfloat16* src = (arr ? g_qs_lo : g_qs_hi) +
                                   ((size_t)h * T_LEN + q0 + r) * HD;
        uint32_t dst = sb0 + arr * Q_BYTES + r * 144;
#pragma unroll
        for (int c = 0; c < 8; c++) cpa16(dst + c * 16, (const char*)src + c * 16);
    }

    int s_begin = (q0 >= WINDOW) ? q0 - WINDOW : 0;
    int nch = (q0 + 64 - s_begin) / 64 + 1;

    attn_load_chunk(sb0, 0, s_begin, h, tid);
    asm volatile("cp.async.commit_group;" ::: "memory");

    float m0 = -1e30f, m1 = -1e30f, l0 = 0.f, l1 = 0.f;
    float O[8][4] = {};
    uint32_t qh[4][4], ql[4][4];

    int ldsA = (wid * 16 + (lane & 15)) * AST + ((lane >> 4) << 3);
    int ldsB_r = ((lane >> 4) << 3) + (lane & 7);
    int ldsB_c = ((lane >> 3) & 1) << 3;
    int qlo_row = q0 + wid * 16 + (lane >> 2);

    for (int i = 0; i < nch; i++) {
        int s0 = s_begin + i * 64;
        if (i + 1 < nch) {
            attn_load_chunk(sb0, (i + 1) & 1, s0 + 64, h, tid);
            asm volatile("cp.async.commit_group;" ::: "memory");
            asm volatile("cp.async.wait_group 1;" ::: "memory");
        } else {
            asm volatile("cp.async.wait_group 0;" ::: "memory");
        }
        __syncthreads();

        if (i == 0) {
#pragma unroll
            for (int kd = 0; kd < 4; kd++) {
                uint32_t qa = sb0 + (ldsA + kd * 16) * 2;
                ldsm_x4(qh[kd][0], qh[kd][1], qh[kd][2], qh[kd][3], qa);
                ldsm_x4(ql[kd][0], ql[kd][1], ql[kd][2], ql[kd][3], qa + Q_BYTES);
            }
        }

        uint32_t stb = sb0 + 2 * Q_BYTES + (i & 1) * KV_STAGE;

        // ---- S = Q @ K^T (3-term) ----
        float S[8][4] = {};
#pragma unroll
        for (int kd = 0; kd < 4; kd++) {
#pragma unroll
            for (int nt16 = 0; nt16 < 4; nt16++) {
                uint32_t ka = stb + ((nt16 * 16 + ldsB_r) * AST + kd * 16 + ldsB_c) * 2;
                uint32_t bh0, bh1, bh2, bh3, bl0, bl1, bl2, bl3;
                ldsm_x4(bh0, bh1, bh2, bh3, ka);
                ldsm_x4(bl0, bl1, bl2, bl3, ka + KV_ARR);
                mma16816(S[2 * nt16], qh[kd][0], qh[kd][1], qh[kd][2], qh[kd][3], bh0, bh1);
                mma16816(S[2 * nt16], qh[kd][0], qh[kd][1], qh[kd][2], qh[kd][3], bl0, bl1);
                mma16816(S[2 * nt16], ql[kd][0], ql[kd][1], ql[kd][2], ql[kd][3], bh0, bh1);
                mma16816(S[2 * nt16 + 1], qh[kd][0], qh[kd][1], qh[kd][2], qh[kd][3], bh2, bh3);
                mma16816(S[2 * nt16 + 1], qh[kd][0], qh[kd][1], qh[kd][2], qh[kd][3], bl2, bl3);
                mma16816(S[2 * nt16 + 1], ql[kd][0], ql[kd][1], ql[kd][2], ql[kd][3], bh2, bh3);
            }
        }

        // ---- mask (boundary chunks only) ----
        if ((s0 + 63 > q0) || (q0 + 127 - s0 >= WINDOW)) {
#pragma unroll
            for (int nt = 0; nt < 8; nt++) {
                int sc = s0 + nt * 8 + (lane & 3) * 2;
#pragma unroll
                for (int e = 0; e < 2; e++) {
                    int d1 = qlo_row - (sc + e);
                    int d2 = d1 + 8;
                    if (d1 < 0 || d1 >= WINDOW) S[nt][e] = -1e30f;
                    if (d2 < 0 || d2 >= WINDOW) S[nt][2 + e] = -1e30f;
                }
            }
        }

        // ---- online softmax (log2 space) ----
        float r0 = -1e30f, r1 = -1e30f;
#pragma unroll
        for (int nt = 0; nt < 8; nt++) {
            r0 = fmaxf(r0, fmaxf(S[nt][0], S[nt][1]));
            r1 = fmaxf(r1, fmaxf(S[nt][2], S[nt][3]));
        }
        r0 = fmaxf(r0, __shfl_xor_sync(0xffffffffu, r0, 1));
        r0 = fmaxf(r0, __shfl_xor_sync(0xffffffffu, r0, 2));
        r1 = fmaxf(r1, __shfl_xor_sync(0xffffffffu, r1, 1));
        r1 = fmaxf(r1, __shfl_xor_sync(0xffffffffu, r1, 2));
        float mn0 = fmaxf(m0, r0), mn1 = fmaxf(m1, r1);
        float al0 = fex2(m0 - mn0), al1 = fex2(m1 - mn1);
        m0 = mn0; m1 = mn1;
        float ps0 = 0.f, ps1 = 0.f;
#pragma unroll
        for (int nt = 0; nt < 8; nt++) {
            S[nt][0] = fex2(S[nt][0] - mn0);
            S[nt][1] = fex2(S[nt][1] - mn0);
            S[nt][2] = fex2(S[nt][2] - mn1);
            S[nt][3] = fex2(S[nt][3] - mn1);
            ps0 += S[nt][0] + S[nt][1];
            ps1 += S[nt][2] + S[nt][3];
        }
        ps0 += __shfl_xor_sync(0xffffffffu, ps0, 1);
        ps0 += __shfl_xor_sync(0xffffffffu, ps0, 2);
        ps1 += __shfl_xor_sync(0xffffffffu, ps1, 1);
        ps1 += __shfl_xor_sync(0xffffffffu, ps1, 2);
        l0 = l0 * al0 + ps0;
        l1 = l1 * al1 + ps1;
#pragma unroll
        for (int nt = 0; nt < 8; nt++) {
            O[nt][0] *= al0; O[nt][1] *= al0;
            O[nt][2] *= al1; O[nt][3] *= al1;
        }

        // ---- O += P @ V (3-term; P split exactly) ----
#pragma unroll
        for (int kc = 0; kc < 4; kc++) {
            uint32_t pa[4], pl[4];
            packpl(S[2 * kc][0],     S[2 * kc][1],     pa[0], pl[0]);
            packpl(S[2 * kc][2],     S[2 * kc][3],     pa[1], pl[1]);
            packpl(S[2 * kc + 1][0], S[2 * kc + 1][1], pa[2], pl[2]);
            packpl(S[2 * kc + 1][2], S[2 * kc + 1][3], pa[3], pl[3]);
#pragma unroll
            for (int dt = 0; dt < 4; dt++) {
                uint32_t va = stb + 2 * KV_ARR +
                              ((dt * 16 + ldsB_r) * AST + kc * 16 + ldsB_c) * 2;
                uint32_t vh0, vh1, vh2, vh3, vl0, vl1, vl2, vl3;
                ldsm_x4(vh0, vh1, vh2, vh3, va);
                ldsm_x4(vl0, vl1, vl2, vl3, va + KV_ARR);
                mma16816(O[2 * dt], pa[0], pa[1], pa[2], pa[3], vh0, vh1);
                mma16816(O[2 * dt], pa[0], pa[1], pa[2], pa[3], vl0, vl1);
                mma16816(O[2 * dt], pl[0], pl[1], pl[2], pl[3], vh0, vh1);
                mma16816(O[2 * dt + 1], pa[0], pa[1], pa[2], pa[3], vh2, vh3);
                mma16816(O[2 * dt + 1], pa[0], pa[1], pa[2], pa[3], vl2, vl3);
                mma16816(O[2 * dt + 1], pl[0], pl[1], pl[2], pl[3], vh2, vh3);
            }
        }
        __syncthreads();
    }

    // ---- epilogue: normalize + bf16 hi/lo split to g_att ----
    float i0 = 1.f / l0, i1 = 1.f / l1;
    int colb = h * HD + (lane & 3) * 2;
#pragma unroll
    for (int nt = 0; nt < 8; nt++) {
        size_t b0 = (size_t)qlo_row * DM + colb + nt * 8;
        size_t b1 = (size_t)(qlo_row + 8) * DM + colb + nt * 8;
        float v0 = O[nt][0] * i0, v1 = O[nt][1] * i0;
        float v2 = O[nt][2] * i1, v3 = O[nt][3] * i1;
        uint32_t ph, pl;
        packpl(v0, v1, ph, pl);
        *(uint32_t*)&g_att_hi[b0] = ph;
        *(uint32_t*)&g_att_lo[b0] = pl;
        packpl(v2, v3, ph, pl);
        *(uint32_t*)&g_att_hi[b1] = ph;
        *(uint32_t*)&g_att_lo[b1] = pl;
    }
}

// ---------------------------------------------------------------------------
extern "C" void kernel_launch(void* const* d_in, const int* in_sizes, int n_in,
                              void* d_out, int out_size)
{
    const float* x     = (const float*)d_in[0];
    const float* w_qkv = (const float*)d_in[3];
    const float* w_o   = (const float*)d_in[4];
    const float* qw    = (const float*)d_in[5];
    const float* kw    = (const float*)d_in[6];
    const float* cosb  = (const float*)d_in[7];
    const float* sinb  = (const float*)d_in[8];
    float* out = (float*)d_out;

    float* qkv_p = nullptr;
    __nv_bfloat16 *xh, *xl, *wqh, *wql, *woh, *wol, *ath, *atl;
    cudaGetSymbolAddress((void**)&qkv_p, g_qkv);
    cudaGetSymbolAddress((void**)&xh, g_x_hi);
    cudaGetSymbolAddress((void**)&xl, g_x_lo);
    cudaGetSymbolAddress((void**)&wqh, g_wqkv_hi);
    cudaGetSymbolAddress((void**)&wql, g_wqkv_lo);
    cudaGetSymbolAddress((void**)&woh, g_wo_hi);
    cudaGetSymbolAddress((void**)&wol, g_wo_lo);
    cudaGetSymbolAddress((void**)&ath, g_att_hi);
    cudaGetSymbolAddress((void**)&atl, g_att_lo);

    static bool attr_done = false;
    if (!attr_done) {
        cudaFuncSetAttribute(gemm_mma, cudaFuncAttributeMaxDynamicSharedMemorySize, 2 * STAGE_B);
        cudaFuncSetAttribute(attn_mma, cudaFuncAttributeMaxDynamicSharedMemorySize, ATTN_SMEM);
        attr_done = true;
    }

    // 0) split inputs to bf16 hi/lo
    cvt_hilo<<<(T_LEN * DM / 4 + 255) / 256, 256>>>(x, xh, xl, T_LEN * DM / 4);
    cvt_hilo<<<(3 * DM * DM / 4 + 255) / 256, 256>>>(w_qkv, wqh, wql, 3 * DM * DM / 4);
    cvt_hilo<<<(DM * DM / 4 + 255) / 256, 256>>>(w_o, woh, wol, DM * DM / 4);

    // 1) qkv = x @ w_qkv^T
    dim3 g1(3 * DM / BN, T_LEN / BM);
    gemm_mma<<<g1, 256, 2 * STAGE_B>>>(xh, xl, wqh, wql, qkv_p, T_LEN, 3 * DM, DM);

    // 2) norm + rope + v-scale, emit bf16 hi/lo (q pre-scaled, v transposed)
    dim3 gp(T_LEN / 32, NH);
    qkv_prep<<<gp, 256>>>(qw, kw, cosb, sinb);

    // 3) tensor-core windowed attention -> att (bf16 hi/lo)
    dim3 ga(T_LEN / 128, NH);
    attn_mma<<<ga, 256, ATTN_SMEM>>>();

    // 4) out = att @ w_o^T
    dim3 g2(DM / BN, T_LEN / BM);
    gemm_mma<<<g2, 256, 2 * STAGE_B>>>(ath, atl, woh, wol, out, T_LEN, DM, DM);
}

// round 10
// speedup vs baseline: 6.8641x; 1.0685x over previous
#include <cuda_runtime.h>
#include <cuda_bf16.h>
#include <math.h>
#include <stdint.h>

#define T_LEN 4096
#define DM 1024
#define NH 16
#define HD 64
#define WINDOW 1024
#define EPS_F 1e-6f
#define QSC 0.17312340490667564f   // 0.12 * log2(e)

// GEMM tiling
#define BM 128
#define BN 128
#define BK 32
#define SA 40
#define STAGE_B 40960
#define ARR_B 10240

// Attention smem geometry
#define AST 72                      // padded row stride (bf16 elems), 144 B
#define Q_BYTES 18432               // 128 * 144 (Q hi array)
#define KV_ARR 9216                 // 64 * 144
#define KV_STAGE 36864              // 4 arrays (also = Q hi+lo region size)
#define ATTN_SMEM (2 * KV_STAGE)    // 73728: Q region doubles as a stage

// ------------------------- scratch (no allocs allowed) ----------------------
__device__ float g_qkv[(size_t)T_LEN * 3 * DM];
__device__ __nv_bfloat16 g_x_hi[(size_t)T_LEN * DM];
__device__ __nv_bfloat16 g_x_lo[(size_t)T_LEN * DM];
__device__ __nv_bfloat16 g_wqkv_hi[(size_t)3 * DM * DM];
__device__ __nv_bfloat16 g_wqkv_lo[(size_t)3 * DM * DM];
__device__ __nv_bfloat16 g_wo_hi[(size_t)DM * DM];
__device__ __nv_bfloat16 g_wo_lo[(size_t)DM * DM];
__device__ __nv_bfloat16 g_att_hi[(size_t)T_LEN * DM];
__device__ __nv_bfloat16 g_att_lo[(size_t)T_LEN * DM];
__device__ __nv_bfloat16 g_qs_hi[(size_t)NH * T_LEN * HD];
__device__ __nv_bfloat16 g_qs_lo[(size_t)NH * T_LEN * HD];
__device__ __nv_bfloat16 g_ks_hi[(size_t)NH * T_LEN * HD];
__device__ __nv_bfloat16 g_ks_lo[(size_t)NH * T_LEN * HD];
__device__ __nv_bfloat16 g_vt_hi[(size_t)NH * HD * T_LEN];
__device__ __nv_bfloat16 g_vt_lo[(size_t)NH * HD * T_LEN];

// ------------------------- helpers ------------------------------------------
__device__ __forceinline__ uint32_t s2u(const void* p) {
    uint32_t a;
    asm("{ .reg .u64 t; cvta.to.shared.u64 t, %1; cvt.u32.u64 %0, t; }"
        : "=r"(a) : "l"(p));
    return a;
}
__device__ __forceinline__ void cpa16(uint32_t dst, const void* src) {
    asm volatile("cp.async.cg.shared.global [%0], [%1], 16;" :: "r"(dst), "l"(src));
}
__device__ __forceinline__ void ldsm_x4(uint32_t& r0, uint32_t& r1,
                                        uint32_t& r2, uint32_t& r3, uint32_t a) {
    asm volatile("ldmatrix.sync.aligned.m8n8.x4.shared.b16 {%0,%1,%2,%3}, [%4];"
                 : "=r"(r0), "=r"(r1), "=r"(r2), "=r"(r3) : "r"(a));
}
__device__ __forceinline__ void mma16816(float* c, uint32_t a0, uint32_t a1,
                                         uint32_t a2, uint32_t a3,
                                         uint32_t b0, uint32_t b1) {
    asm volatile(
        "mma.sync.aligned.m16n8k16.row.col.f32.bf16.bf16.f32 "
        "{%0,%1,%2,%3}, {%4,%5,%6,%7}, {%8,%9}, {%0,%1,%2,%3};"
        : "+f"(c[0]), "+f"(c[1]), "+f"(c[2]), "+f"(c[3])
        : "r"(a0), "r"(a1), "r"(a2), "r"(a3), "r"(b0), "r"(b1));
}
__device__ __forceinline__ float fex2(float x) {
    float y;
    asm("ex2.approx.ftz.f32 %0, %1;" : "=f"(y) : "f"(x));
    return y;
}
__device__ __forceinline__ uint32_t packbf2(float a, float b) {
    __nv_bfloat162 p = __halves2bfloat162(__float2bfloat16(a), __float2bfloat16(b));
    return *(uint32_t*)&p;
}
__device__ __forceinline__ void packpl(float p0, float p1, uint32_t& hi, uint32_t& lo) {
    __nv_bfloat16 h0 = __float2bfloat16(p0), h1 = __float2bfloat16(p1);
    __nv_bfloat162 hp = __halves2bfloat162(h0, h1);
    hi = *(uint32_t*)&hp;
    __nv_bfloat162 lp = __halves2bfloat162(__float2bfloat16(p0 - __bfloat162float(h0)),
                                           __float2bfloat16(p1 - __bfloat162float(h1)));
    lo = *(uint32_t*)&lp;
}

// ---------------------------------------------------------------------------
// fp32 -> (bf16 hi, bf16 lo) split
// ---------------------------------------------------------------------------
__global__ __launch_bounds__(256) void cvt_hilo(const float* __restrict__ in,
                                                __nv_bfloat16* __restrict__ hi,
                                                __nv_bfloat16* __restrict__ lo,
                                                int n4)
{
    int i = blockIdx.x * 256 + threadIdx.x;
    if (i >= n4) return;
    float4 v = ((const float4*)in)[i];
    ((uint32_t*)hi)[2 * i]     = packbf2(v.x, v.y);
    ((uint32_t*)hi)[2 * i + 1] = packbf2(v.z, v.w);
    float hx = __bfloat162float(__float2bfloat16(v.x));
    float hy = __bfloat162float(__float2bfloat16(v.y));
    float hz = __bfloat162float(__float2bfloat16(v.z));
    float hw = __bfloat162float(__float2bfloat16(v.w));
    ((uint32_t*)lo)[2 * i]     = packbf2(v.x - hx, v.y - hy);
    ((uint32_t*)lo)[2 * i + 1] = packbf2(v.z - hz, v.w - hw);
}

// ---------------------------------------------------------------------------
// mma.sync GEMM — now 2 CTAs/SM (regs clamped to 128)
// ---------------------------------------------------------------------------
extern __shared__ __align__(128) char gsm[];

__global__ __launch_bounds__(256, 2) void gemm_mma(const __nv_bfloat16* __restrict__ Ahi,
                                                   const __nv_bfloat16* __restrict__ Alo,
                                                   const __nv_bfloat16* __restrict__ Bhi,
                                                   const __nv_bfloat16* __restrict__ Blo,
                                                   float* __restrict__ C,
                                                   int M, int N, int K)
{
    uint32_t sbase = s2u(gsm);
    int tid = threadIdx.x;
    int wid = tid >> 5;
    int lane = tid & 31;
    int wm = (wid >> 2) * 64;
    int wn = (wid & 3) * 32;
    int row0 = blockIdx.y * BM;
    int col0 = blockIdx.x * BN;

    int lrow = tid >> 2;
    int lkc = tid & 3;
    const char* gAh = (const char*)(Ahi + (size_t)(row0 + lrow) * K + lkc * 8);
    const char* gAl = (const char*)(Alo + (size_t)(row0 + lrow) * K + lkc * 8);
    const char* gBh = (const char*)(Bhi + (size_t)(col0 + lrow) * K + lkc * 8);
    const char* gBl = (const char*)(Blo + (size_t)(col0 + lrow) * K + lkc * 8);
    size_t gstep = (size_t)64 * K * 2;
    uint32_t soff0 = lrow * 80 + lkc * 16;
    uint32_t soff1 = soff0 + 64 * 80;

#define LOAD_STAGE(st, k0)                                                  \
    do {                                                                    \
        uint32_t sb = sbase + (st) * STAGE_B;                               \
        size_t go = (size_t)(k0) * 2;                                       \
        cpa16(sb + soff0,             gAh + go);                            \
        cpa16(sb + soff1,             gAh + go + gstep);                    \
        cpa16(sb + ARR_B + soff0,     gAl + go);                            \
        cpa16(sb + ARR_B + soff1,     gAl + go + gstep);                    \
        cpa16(sb + 2 * ARR_B + soff0, gBh + go);                            \
        cpa16(sb + 2 * ARR_B + soff1, gBh + go + gstep);                    \
        cpa16(sb + 3 * ARR_B + soff0, gBl + go);                            \
        cpa16(sb + 3 * ARR_B + soff1, gBl + go + gstep);                    \
    } while (0)

    float acc[4][4][4] = {};

    int a_r = wm + (lane & 15);
    int a_c0 = (lane >> 4) << 3;
    int b_r = wn + ((lane >> 4) << 3) + (lane & 7);
    int b_c0 = ((lane >> 3) & 1) << 3;

    LOAD_STAGE(0, 0);
    asm volatile("cp.async.commit_group;" ::: "memory");

    const int NKT = K / BK;
    for (int kt = 0; kt < NKT; kt++) {
        if (kt + 1 < NKT) {
            LOAD_STAGE((kt + 1) & 1, (kt + 1) * BK);
            asm volatile("cp.async.commit_group;" ::: "memory");
            asm volatile("cp.async.wait_group 1;" ::: "memory");
        } else {
            asm volatile("cp.async.commit_group;" ::: "memory");
            asm volatile("cp.async.wait_group 0;" ::: "memory");
        }
        __syncthreads();

        uint32_t stb = sbase + (kt & 1) * STAGE_B;
#pragma unroll
        for (int ks = 0; ks < 2; ks++) {
            uint32_t ah[4][4], al[4][4];
            int acol = ks * 16 + a_c0;
#pragma unroll
            for (int mt = 0; mt < 4; mt++) {
                uint32_t aaddr = stb + ((a_r + mt * 16) * SA + acol) * 2;
                ldsm_x4(ah[mt][0], ah[mt][1], ah[mt][2], ah[mt][3], aaddr);
                ldsm_x4(al[mt][0], al[mt][1], al[mt][2], al[mt][3], aaddr + ARR_B);
            }
            int bcol = ks * 16 + b_c0;
#pragma unroll
            for (int nt2 = 0; nt2 < 2; nt2++) {
                uint32_t bh0, bh1, bh2, bh3, bl0, bl1, bl2, bl3;
                uint32_t baddr = stb + 2 * ARR_B + ((b_r + nt2 * 16) * SA + bcol) * 2;
                ldsm_x4(bh0, bh1, bh2, bh3, baddr);
                ldsm_x4(bl0, bl1, bl2, bl3, baddr + ARR_B);
#pragma unroll
                for (int mt = 0; mt < 4; mt++) {
                    mma16816(acc[mt][2 * nt2], ah[mt][0], ah[mt][1], ah[mt][2], ah[mt][3], bh0, bh1);
                    mma16816(acc[mt][2 * nt2], ah[mt][0], ah[mt][1], ah[mt][2], ah[mt][3], bl0, bl1);
                    mma16816(acc[mt][2 * nt2], al[mt][0], al[mt][1], al[mt][2], al[mt][3], bh0, bh1);
                    mma16816(acc[mt][2 * nt2 + 1], ah[mt][0], ah[mt][1], ah[mt][2], ah[mt][3], bh2, bh3);
                    mma16816(acc[mt][2 * nt2 + 1], ah[mt][0], ah[mt][1], ah[mt][2], ah[mt][3], bl2, bl3);
                    mma16816(acc[mt][2 * nt2 + 1], al[mt][0], al[mt][1], al[mt][2], al[mt][3], bh2, bh3);
                }
            }
        }
        __syncthreads();
    }
#undef LOAD_STAGE

    int erow = row0 + wm + (lane >> 2);
    int ecol0 = col0 + wn + (lane & 3) * 2;
#pragma unroll
    for (int mt = 0; mt < 4; mt++) {
#pragma unroll
        for (int nt = 0; nt < 4; nt++) {
            float* c = acc[mt][nt];
            size_t r0i = (size_t)(erow + mt * 16) * N + ecol0 + nt * 8;
            *(float2*)&C[r0i]         = make_float2(c[0], c[1]);
            *(float2*)&C[r0i + 8 * N] = make_float2(c[2], c[3]);
        }
    }
}

// ---------------------------------------------------------------------------
// qkv_prep (unchanged)
// ---------------------------------------------------------------------------
__global__ __launch_bounds__(256) void qkv_prep(const float* __restrict__ qw,
                                                const float* __restrict__ kw,
                                                const float* __restrict__ cosb,
                                                const float* __restrict__ sinb)
{
    __shared__ float vt_s[64][33];
    int tid = threadIdx.x;
    int wid = tid >> 5, lane = tid & 31;
    int h = blockIdx.y;
    int t0 = blockIdx.x * 32;

#pragma unroll
    for (int j = 0; j < 4; j++) {
        int tl = wid * 4 + j;
        int t = t0 + tl;
        const float* rowbase = g_qkv + (size_t)t * (3 * DM) + h * HD;
        float2 qv = ((const float2*)rowbase)[lane];
        float2 kv = ((const float2*)(rowbase + DM))[lane];
        float2 vv = ((const float2*)(rowbase + 2 * DM))[lane];

        float sq = qv.x * qv.x + qv.y * qv.y;
        float sk = kv.x * kv.x + kv.y * kv.y;
#pragma unroll
        for (int off = 16; off; off >>= 1) {
            sq += __shfl_xor_sync(0xffffffffu, sq, off);
            sk += __shfl_xor_sync(0xffffffffu, sk, off);
        }
        float rq = rsqrtf(sq * (1.f / 64.f) + EPS_F);
        float rk = rsqrtf(sk * (1.f / 64.f) + EPS_F);

        int d0 = lane * 2;
        float q0 = qv.x * rq * qw[d0], q1 = qv.y * rq * qw[d0 + 1];
        float k0 = kv.x * rk * kw[d0], k1 = kv.y * rk * kw[d0 + 1];

        if (lane < 16) {
            float c = cosb[t * 16 + lane];
            float s = sinb[t * 16 + lane];
            float e = q0, o = q1;
            q0 = e * c - o * s;  q1 = e * s + o * c;
            e = k0; o = k1;
            k0 = e * c - o * s;  k1 = e * s + o * c;
        }
        q0 *= QSC; q1 *= QSC;

        size_t base = ((size_t)h * T_LEN + t) * HD + d0;
        uint32_t ph, pl;
        packpl(q0, q1, ph, pl);
        *(uint32_t*)&g_qs_hi[base] = ph;
        *(uint32_t*)&g_qs_lo[base] = pl;
        packpl(k0, k1, ph, pl);
        *(uint32_t*)&g_ks_hi[base] = ph;
        *(uint32_t*)&g_ks_lo[base] = pl;

        vt_s[d0][tl]     = vv.x * 0.5f;
        vt_s[d0 + 1][tl] = vv.y * 0.5f;
    }
    __syncthreads();

    int d = tid >> 2;
    int tg = (tid & 3) * 8;
    uint32_t hi[4], lo[4];
#pragma unroll
    for (int i = 0; i < 4; i++) {
        float a = vt_s[d][tg + 2 * i], b = vt_s[d][tg + 2 * i + 1];
        packpl(a, b, hi[i], lo[i]);
    }
    size_t vbase = ((size_t)h * HD + d) * T_LEN + t0 + tg;
    *(uint4*)&g_vt_hi[vbase] = make_uint4(hi[0], hi[1], hi[2], hi[3]);
    *(uint4*)&g_vt_lo[vbase] = make_uint4(lo[0], lo[1], lo[2], lo[3]);
}

// ---------------------------------------------------------------------------
// Tensor-core flash attention, 2 CTAs/SM.
// SMEM: two 36.9KB regions; Q (hi+lo) loaded into R0, fragments extracted once,
// then R0/R1 ping-pong as KV stages: stage(i) = i even ? R1 : R0.
// ---------------------------------------------------------------------------
__device__ __forceinline__ void attn_load_chunk(uint32_t dstbase, int s0,
                                                int h, int tid)
{
    int arr = tid >> 6, r = tid & 63;
    uint32_t dst = dstbase + arr * KV_ARR + r * 144;
    const __nv_bfloat16* src;
    if (arr == 0)      src = g_ks_hi + ((size_t)h * T_LEN + s0 + r) * HD;
    else if (arr == 1) src = g_ks_lo + ((size_t)h * T_LEN + s0 + r) * HD;
    else if (arr == 2) src = g_vt_hi + ((size_t)h * HD + r) * T_LEN + s0;
    else               src = g_vt_lo + ((size_t)h * HD + r) * T_LEN + s0;
#pragma unroll
    for (int c = 0; c < 8; c++) cpa16(dst + c * 16, (const char*)src + c * 16);
}

__global__ __launch_bounds__(256, 2) void attn_mma()
{
    uint32_t sb0 = s2u(gsm);
    uint32_t R0 = sb0, R1 = sb0 + KV_STAGE;
    int tid = threadIdx.x;
    int wid = tid >> 5, lane = tid & 31;
    int h = blockIdx.y;
    int q0 = blockIdx.x * 128;

    // Q loads (hi at R0, lo at R0+Q_BYTES)
    {
        int arr = tid >> 7, r = tid & 127;
        const __nv_bfloat16* src = (arr ? g_qs_lo : g_qs_hi) +
                                   ((size_t)h * T_LEN + q0 + r) * HD;
        uint32_t dst = R0 + arr * Q_BYTES + r * 144;
#pragma unroll
        for (int c = 0; c < 8; c++) cpa16(dst + c * 16, (const char*)src + c * 16);
    }

    int s_begin = (q0 >= WINDOW) ? q0 - WINDOW : 0;
    int nch = (q0 + 64 - s_begin) / 64 + 1;

    attn_load_chunk(R1, s_begin, h, tid);            // chunk 0 -> R1
    asm volatile("cp.async.commit_group;" ::: "memory");
    asm volatile("cp.async.wait_group 0;" ::: "memory");
    __syncthreads();

    int ldsA = (wid * 16 + (lane & 15)) * AST + ((lane >> 4) << 3);
    int ldsB_r = ((lane >> 4) << 3) + (lane & 7);
    int ldsB_c = ((lane >> 3) & 1) << 3;
    int qlo_row = q0 + wid * 16 + (lane >> 2);

    // extract Q fragments (then R0 becomes a free stage)
    uint32_t qh[4][4], ql[4][4];
#pragma unroll
    for (int kd = 0; kd < 4; kd++) {
        uint32_t qa = R0 + (ldsA + kd * 16) * 2;
        ldsm_x4(qh[kd][0], qh[kd][1], qh[kd][2], qh[kd][3], qa);
        ldsm_x4(ql[kd][0], ql[kd][1], ql[kd][2], ql[kd][3], qa + Q_BYTES);
    }
    __syncthreads();

    float m0 = -1e30f, m1 = -1e30f, l0 = 0.f, l1 = 0.f;
    float O[8][4] = {};

    for (int i = 0; i < nch; i++) {
        int s0 = s_begin + i * 64;
        uint32_t stb = (i & 1) ? R0 : R1;
        if (i + 1 < nch) {
            attn_load_chunk((i & 1) ? R1 : R0, s0 + 64, h, tid);
            asm volatile("cp.async.commit_group;" ::: "memory");
            asm volatile("cp.async.wait_group 1;" ::: "memory");
        } else {
            asm volatile("cp.async.wait_group 0;" ::: "memory");
        }
        __syncthreads();

        // ---- S = Q @ K^T (3-term) ----
        float S[8][4] = {};
#pragma unroll
        for (int kd = 0; kd < 4; kd++) {
#pragma unroll
            for (int nt16 = 0; nt16 < 4; nt16++) {
                uint32_t ka = stb + ((nt16 * 16 + ldsB_r) * AST + kd * 16 + ldsB_c) * 2;
                uint32_t bh0, bh1, bh2, bh3, bl0, bl1, bl2, bl3;
                ldsm_x4(bh0, bh1, bh2, bh3, ka);
                ldsm_x4(bl0, bl1, bl2, bl3, ka + KV_ARR);
                mma16816(S[2 * nt16], qh[kd][0], qh[kd][1], qh[kd][2], qh[kd][3], bh0, bh1);
                mma16816(S[2 * nt16], qh[kd][0], qh[kd][1], qh[kd][2], qh[kd][3], bl0, bl1);
                mma16816(S[2 * nt16], ql[kd][0], ql[kd][1], ql[kd][2], ql[kd][3], bh0, bh1);
                mma16816(S[2 * nt16 + 1], qh[kd][0], qh[kd][1], qh[kd][2], qh[kd][3], bh2, bh3);
                mma16816(S[2 * nt16 + 1], qh[kd][0], qh[kd][1], qh[kd][2], qh[kd][3], bl2, bl3);
                mma16816(S[2 * nt16 + 1], ql[kd][0], ql[kd][1], ql[kd][2], ql[kd][3], bh2, bh3);
            }
        }

        // ---- mask (boundary chunks only) ----
        if ((s0 + 63 > q0) || (q0 + 127 - s0 >= WINDOW)) {
#pragma unroll
            for (int nt = 0; nt < 8; nt++) {
                int sc = s0 + nt * 8 + (lane & 3) * 2;
#pragma unroll
                for (int e = 0; e < 2; e++) {
                    int d1 = qlo_row - (sc + e);
                    int d2 = d1 + 8;
                    if (d1 < 0 || d1 >= WINDOW) S[nt][e] = -1e30f;
                    if (d2 < 0 || d2 >= WINDOW) S[nt][2 + e] = -1e30f;
                }
            }
        }

        // ---- online softmax (log2 space) ----
        float r0 = -1e30f, r1 = -1e30f;
#pragma unroll
        for (int nt = 0; nt < 8; nt++) {
            r0 = fmaxf(r0, fmaxf(S[nt][0], S[nt][1]));
            r1 = fmaxf(r1, fmaxf(S[nt][2], S[nt][3]));
        }
        r0 = fmaxf(r0, __shfl_xor_sync(0xffffffffu, r0, 1));
        r0 = fmaxf(r0, __shfl_xor_sync(0xffffffffu, r0, 2));
        r1 = fmaxf(r1, __shfl_xor_sync(0xffffffffu, r1, 1));
        r1 = fmaxf(r1, __shfl_xor_sync(0xffffffffu, r1, 2));
        float mn0 = fmaxf(m0, r0), mn1 = fmaxf(m1, r1);
        float al0 = fex2(m0 - mn0), al1 = fex2(m1 - mn1);
        m0 = mn0; m1 = mn1;
        float ps0 = 0.f, ps1 = 0.f;
#pragma unroll
        for (int nt = 0; nt < 8; nt++) {
            S[nt][0] = fex2(S[nt][0] - mn0);
            S[nt][1] = fex2(S[nt][1] - mn0);
            S[nt][2] = fex2(S[nt][2] - mn1);
            S[nt][3] = fex2(S[nt][3] - mn1);
            ps0 += S[nt][0] + S[nt][1];
            ps1 += S[nt][2] + S[nt][3];
        }
        ps0 += __shfl_xor_sync(0xffffffffu, ps0, 1);
        ps0 += __shfl_xor_sync(0xffffffffu, ps0, 2);
        ps1 += __shfl_xor_sync(0xffffffffu, ps1, 1);
        ps1 += __shfl_xor_sync(0xffffffffu, ps1, 2);
        l0 = l0 * al0 + ps0;
        l1 = l1 * al1 + ps1;
#pragma unroll
        for (int nt = 0; nt < 8; nt++) {
            O[nt][0] *= al0; O[nt][1] *= al0;
            O[nt][2] *= al1; O[nt][3] *= al1;
        }

        // ---- O += P @ V (3-term; P split exactly) ----
#pragma unroll
        for (int kc = 0; kc < 4; kc++) {
            uint32_t pa[4], pl[4];
            packpl(S[2 * kc][0],     S[2 * kc][1],     pa[0], pl[0]);
            packpl(S[2 * kc][2],     S[2 * kc][3],     pa[1], pl[1]);
            packpl(S[2 * kc + 1][0], S[2 * kc + 1][1], pa[2], pl[2]);
            packpl(S[2 * kc + 1][2], S[2 * kc + 1][3], pa[3], pl[3]);
#pragma unroll
            for (int dt = 0; dt < 4; dt++) {
                uint32_t va = stb + 2 * KV_ARR +
                              ((dt * 16 + ldsB_r) * AST + kc * 16 + ldsB_c) * 2;
                uint32_t vh0, vh1, vh2, vh3, vl0, vl1, vl2, vl3;
                ldsm_x4(vh0, vh1, vh2, vh3, va);
                ldsm_x4(vl0, vl1, vl2, vl3, va + KV_ARR);
                mma16816(O[2 * dt], pa[0], pa[1], pa[2], pa[3], vh0, vh1);
                mma16816(O[2 * dt], pa[0], pa[1], pa[2], pa[3], vl0, vl1);
                mma16816(O[2 * dt], pl[0], pl[1], pl[2], pl[3], vh0, vh1);
                mma16816(O[2 * dt + 1], pa[0], pa[1], pa[2], pa[3], vh2, vh3);
                mma16816(O[2 * dt + 1], pa[0], pa[1], pa[2], pa[3], vl2, vl3);
                mma16816(O[2 * dt + 1], pl[0], pl[1], pl[2], pl[3], vh2, vh3);
            }
        }
        __syncthreads();
    }

    // ---- epilogue ----
    float i0 = 1.f / l0, i1 = 1.f / l1;
    int colb = h * HD + (lane & 3) * 2;
#pragma unroll
    for (int nt = 0; nt < 8; nt++) {
        size_t b0 = (size_t)qlo_row * DM + colb + nt * 8;
        size_t b1 = (size_t)(qlo_row + 8) * DM + colb + nt * 8;
        float v0 = O[nt][0] * i0, v1 = O[nt][1] * i0;
        float v2 = O[nt][2] * i1, v3 = O[nt][3] * i1;
        uint32_t ph, pl;
        packpl(v0, v1, ph, pl);
        *(uint32_t*)&g_att_hi[b0] = ph;
        *(uint32_t*)&g_att_lo[b0] = pl;
        packpl(v2, v3, ph, pl);
        *(uint32_t*)&g_att_hi[b1] = ph;
        *(uint32_t*)&g_att_lo[b1] = pl;
    }
}

// ---------------------------------------------------------------------------
extern "C" void kernel_launch(void* const* d_in, const int* in_sizes, int n_in,
                              void* d_out, int out_size)
{
    const float* x     = (const float*)d_in[0];
    const float* w_qkv = (const float*)d_in[3];
    const float* w_o   = (const float*)d_in[4];
    const float* qw    = (const float*)d_in[5];
    const float* kw    = (const float*)d_in[6];
    const float* cosb  = (const float*)d_in[7];
    const float* sinb  = (const float*)d_in[8];
    float* out = (float*)d_out;

    float* qkv_p = nullptr;
    __nv_bfloat16 *xh, *xl, *wqh, *wql, *woh, *wol, *ath, *atl;
    cudaGetSymbolAddress((void**)&qkv_p, g_qkv);
    cudaGetSymbolAddress((void**)&xh, g_x_hi);
    cudaGetSymbolAddress((void**)&xl, g_x_lo);
    cudaGetSymbolAddress((void**)&wqh, g_wqkv_hi);
    cudaGetSymbolAddress((void**)&wql, g_wqkv_lo);
    cudaGetSymbolAddress((void**)&woh, g_wo_hi);
    cudaGetSymbolAddress((void**)&wol, g_wo_lo);
    cudaGetSymbolAddress((void**)&ath, g_att_hi);
    cudaGetSymbolAddress((void**)&atl, g_att_lo);

    static bool attr_done = false;
    if (!attr_done) {
        cudaFuncSetAttribute(gemm_mma, cudaFuncAttributeMaxDynamicSharedMemorySize, 2 * STAGE_B);
        cudaFuncSetAttribute(attn_mma, cudaFuncAttributeMaxDynamicSharedMemorySize, ATTN_SMEM);
        attr_done = true;
    }

    // 0) split inputs to bf16 hi/lo
    cvt_hilo<<<(T_LEN * DM / 4 + 255) / 256, 256>>>(x, xh, xl, T_LEN * DM / 4);
    cvt_hilo<<<(3 * DM * DM / 4 + 255) / 256, 256>>>(w_qkv, wqh, wql, 3 * DM * DM / 4);
    cvt_hilo<<<(DM * DM / 4 + 255) / 256, 256>>>(w_o, woh, wol, DM * DM / 4);

    // 1) qkv = x @ w_qkv^T
    dim3 g1(3 * DM / BN, T_LEN / BM);
    gemm_mma<<<g1, 256, 2 * STAGE_B>>>(xh, xl, wqh, wql, qkv_p, T_LEN, 3 * DM, DM);

    // 2) norm + rope + v-scale, emit bf16 hi/lo
    dim3 gp(T_LEN / 32, NH);
    qkv_prep<<<gp, 256>>>(qw, kw, cosb, sinb);

    // 3) tensor-core windowed attention -> att (bf16 hi/lo)
    dim3 ga(T_LEN / 128, NH);
    attn_mma<<<ga, 256, ATTN_SMEM>>>();

    // 4) out = att @ w_o^T
    dim3 g2(DM / BN, T_LEN / BM);
    gemm_mma<<<g2, 256, 2 * STAGE_B>>>(ath, atl, woh, wol, out, T_LEN, DM, DM);
}

// round 13
// speedup vs baseline: 7.6875x; 1.1200x over previous
#include <cuda_runtime.h>
#include <cuda_bf16.h>
#include <math.h>
#include <stdint.h>

#define T_LEN 4096
#define DM 1024
#define NH 16
#define HD 64
#define WINDOW 1024
#define EPS_F 1e-6f
#define QSC 0.17312340490667564f   // 0.12 * log2(e)

// GEMM tiling: 128x128, BK=32, 64B rows, swizzle chunk^=(row>>1)&3
#define BM 128
#define BN 128
#define BK 32
#define G_ARR 8192                  // 128 rows * 64 B
#define G_STAGE 32768               // 4 arrays
#define G_SMEM (3 * G_STAGE)        // 98304

// Attention: 128B rows, SW128 swizzle chunk^=row&7
#define A_KARR 8192                 // 64 rows * 128 B
#define A_STAGE 32768               // Khi Klo Vhi Vlo
#define A_QARR 16384                // 128 rows * 128 B
#define A_SMEM (3 * A_STAGE)        // 98304 (region0 = Q hi+lo initially)

// ------------------------- scratch (no allocs allowed) ----------------------
__device__ float g_qkv[(size_t)T_LEN * 3 * DM];
__device__ __nv_bfloat16 g_x_hi[(size_t)T_LEN * DM];
__device__ __nv_bfloat16 g_x_lo[(size_t)T_LEN * DM];
__device__ __nv_bfloat16 g_wqkv_hi[(size_t)3 * DM * DM];
__device__ __nv_bfloat16 g_wqkv_lo[(size_t)3 * DM * DM];
__device__ __nv_bfloat16 g_wo_hi[(size_t)DM * DM];
__device__ __nv_bfloat16 g_wo_lo[(size_t)DM * DM];
__device__ __nv_bfloat16 g_att_hi[(size_t)T_LEN * DM];
__device__ __nv_bfloat16 g_att_lo[(size_t)T_LEN * DM];
__device__ __nv_bfloat16 g_qs_hi[(size_t)NH * T_LEN * HD];
__device__ __nv_bfloat16 g_qs_lo[(size_t)NH * T_LEN * HD];
__device__ __nv_bfloat16 g_ks_hi[(size_t)NH * T_LEN * HD];
__device__ __nv_bfloat16 g_ks_lo[(size_t)NH * T_LEN * HD];
__device__ __nv_bfloat16 g_vt_hi[(size_t)NH * HD * T_LEN];
__device__ __nv_bfloat16 g_vt_lo[(size_t)NH * HD * T_LEN];

// ------------------------- helpers ------------------------------------------
__device__ __forceinline__ uint32_t s2u(const void* p) {
    uint32_t a;
    asm("{ .reg .u64 t; cvta.to.shared.u64 t, %1; cvt.u32.u64 %0, t; }"
        : "=r"(a) : "l"(p));
    return a;
}
__device__ __forceinline__ void cpa16(uint32_t dst, const void* src) {
    asm volatile("cp.async.cg.shared.global [%0], [%1], 16;" :: "r"(dst), "l"(src));
}
#define CP_COMMIT() asm volatile("cp.async.commit_group;" ::: "memory")
#define CP_WAIT(n)  asm volatile("cp.async.wait_group %0;" :: "n"(n) : "memory")
__device__ __forceinline__ void ldsm_x4(uint32_t& r0, uint32_t& r1,
                                        uint32_t& r2, uint32_t& r3, uint32_t a) {
    asm volatile("ldmatrix.sync.aligned.m8n8.x4.shared.b16 {%0,%1,%2,%3}, [%4];"
                 : "=r"(r0), "=r"(r1), "=r"(r2), "=r"(r3) : "r"(a));
}
__device__ __forceinline__ void mma16816(float* c, const uint32_t* a,
                                         uint32_t b0, uint32_t b1) {
    asm volatile(
        "mma.sync.aligned.m16n8k16.row.col.f32.bf16.bf16.f32 "
        "{%0,%1,%2,%3}, {%4,%5,%6,%7}, {%8,%9}, {%0,%1,%2,%3};"
        : "+f"(c[0]), "+f"(c[1]), "+f"(c[2]), "+f"(c[3])
        : "r"(a[0]), "r"(a[1]), "r"(a[2]), "r"(a[3]), "r"(b0), "r"(b1));
}
__device__ __forceinline__ float fex2(float x) {
    float y;
    asm("ex2.approx.ftz.f32 %0, %1;" : "=f"(y) : "f"(x));
    return y;
}
__device__ __forceinline__ uint32_t packbf2(float a, float b) {
    __nv_bfloat162 p = __halves2bfloat162(__float2bfloat16(a), __float2bfloat16(b));
    return *(uint32_t*)&p;
}
__device__ __forceinline__ void packpl(float p0, float p1, uint32_t& hi, uint32_t& lo) {
    __nv_bfloat16 h0 = __float2bfloat16(p0), h1 = __float2bfloat16(p1);
    __nv_bfloat162 hp = __halves2bfloat162(h0, h1);
    hi = *(uint32_t*)&hp;
    __nv_bfloat162 lp = __halves2bfloat162(__float2bfloat16(p0 - __bfloat162float(h0)),
                                           __float2bfloat16(p1 - __bfloat162float(h1)));
    lo = *(uint32_t*)&lp;
}

// ---------------------------------------------------------------------------
// fp32 -> (bf16 hi, bf16 lo) split
// ---------------------------------------------------------------------------
__global__ __launch_bounds__(256) void cvt_hilo(const float* __restrict__ in,
                                                __nv_bfloat16* __restrict__ hi,
                                                __nv_bfloat16* __restrict__ lo,
                                                int n4)
{
    int i = blockIdx.x * 256 + threadIdx.x;
    if (i >= n4) return;
    float4 v = ((const float4*)in)[i];
    ((uint32_t*)hi)[2 * i]     = packbf2(v.x, v.y);
    ((uint32_t*)hi)[2 * i + 1] = packbf2(v.z, v.w);
    float hx = __bfloat162float(__float2bfloat16(v.x));
    float hy = __bfloat162float(__float2bfloat16(v.y));
    float hz = __bfloat162float(__float2bfloat16(v.z));
    float hw = __bfloat162float(__float2bfloat16(v.w));
    ((uint32_t*)lo)[2 * i]     = packbf2(v.x - hx, v.y - hy);
    ((uint32_t*)lo)[2 * i + 1] = packbf2(v.z - hz, v.w - hw);
}

// ---------------------------------------------------------------------------
// mma.sync GEMM: 3-stage pipeline, 1 sync/iter, term-major MMA order,
// swizzled 64B-row smem. 2 CTAs/SM.
// ---------------------------------------------------------------------------
extern __shared__ __align__(128) char gsm[];

__global__ __launch_bounds__(256, 2) void gemm_mma(const __nv_bfloat16* __restrict__ Ahi,
                                                   const __nv_bfloat16* __restrict__ Alo,
                                                   const __nv_bfloat16* __restrict__ Bhi,
                                                   const __nv_bfloat16* __restrict__ Blo,
                                                   float* __restrict__ C,
                                                   int M, int N, int K)
{
    uint32_t sbase = s2u(gsm);
    int tid = threadIdx.x;
    int wid = tid >> 5;
    int lane = tid & 31;
    int wm = (wid >> 2) * 64;
    int wn = (wid & 3) * 32;
    int row0 = blockIdx.y * BM;
    int col0 = blockIdx.x * BN;

    // loader: thread -> rows (lrow, lrow+64), 16B chunk lkc
    int lrow = tid >> 2;
    int lkc = tid & 3;
    const char* gAh = (const char*)(Ahi + (size_t)(row0 + lrow) * K + lkc * 8);
    const char* gAl = (const char*)(Alo + (size_t)(row0 + lrow) * K + lkc * 8);
    const char* gBh = (const char*)(Bhi + (size_t)(col0 + lrow) * K + lkc * 8);
    const char* gBl = (const char*)(Blo + (size_t)(col0 + lrow) * K + lkc * 8);
    size_t gstep = (size_t)64 * K * 2;
    uint32_t sw0 = lrow * 64 + ((lkc ^ ((lrow >> 1) & 3)) << 4);
    uint32_t sw1 = sw0 + 64 * 64;      // +64 rows: same swizzle phase

#define LOAD_STAGE(st, k0)                                                  \
    do {                                                                    \
        uint32_t sb = sbase + (st) * G_STAGE;                               \
        size_t go = (size_t)(k0) * 2;                                       \
        cpa16(sb + sw0,             gAh + go);                              \
        cpa16(sb + sw1,             gAh + go + gstep);                      \
        cpa16(sb + G_ARR + sw0,     gAl + go);                              \
        cpa16(sb + G_ARR + sw1,     gAl + go + gstep);                      \
        cpa16(sb + 2 * G_ARR + sw0, gBh + go);                              \
        cpa16(sb + 2 * G_ARR + sw1, gBh + go + gstep);                      \
        cpa16(sb + 3 * G_ARR + sw0, gBl + go);                              \
        cpa16(sb + 3 * G_ARR + sw1, gBl + go + gstep);                      \
    } while (0)

    float acc[4][4][4] = {};

    int a_r = wm + (lane & 15);
    uint32_t s_a = ((lane & 15) >> 1) & 3;            // swizzle XOR for A rows
    int b_r = wn + ((lane >> 4) << 3) + (lane & 7);
    uint32_t s_b = (((((lane >> 4) << 3) + (lane & 7))) >> 1) & 3;
    uint32_t a_cb = lane >> 4;                        // chunk bit for A
    uint32_t b_cb = (lane >> 3) & 1;                  // chunk bit for B

    LOAD_STAGE(0, 0);
    CP_COMMIT();
    LOAD_STAGE(1, BK);
    CP_COMMIT();

    const int NKT = K / BK;
    for (int kt = 0; kt < NKT; kt++) {
        CP_WAIT(1);
        __syncthreads();
        if (kt + 2 < NKT) LOAD_STAGE((kt + 2) % 3, (kt + 2) * BK);
        CP_COMMIT();

        uint32_t stb = sbase + (kt % 3) * G_STAGE;
#pragma unroll
        for (int ks = 0; ks < 2; ks++) {
            uint32_t ah[4][4], al[4][4];
            uint32_t acsw = ((ks * 2 + a_cb) ^ s_a) << 4;
#pragma unroll
            for (int mt = 0; mt < 4; mt++) {
                uint32_t aaddr = stb + (a_r + mt * 16) * 64 + acsw;
                ldsm_x4(ah[mt][0], ah[mt][1], ah[mt][2], ah[mt][3], aaddr);
                ldsm_x4(al[mt][0], al[mt][1], al[mt][2], al[mt][3], aaddr + G_ARR);
            }
            uint32_t bcsw = ((ks * 2 + b_cb) ^ s_b) << 4;
#pragma unroll
            for (int nt2 = 0; nt2 < 2; nt2++) {
                uint32_t bh[4], bl[4];
                uint32_t baddr = stb + 2 * G_ARR + (b_r + nt2 * 16) * 64 + bcsw;
                ldsm_x4(bh[0], bh[1], bh[2], bh[3], baddr);
                ldsm_x4(bl[0], bl[1], bl[2], bl[3], baddr + G_ARR);
                // term hh
#pragma unroll
                for (int mt = 0; mt < 4; mt++) {
                    mma16816(acc[mt][2 * nt2],     ah[mt], bh[0], bh[1]);
                    mma16816(acc[mt][2 * nt2 + 1], ah[mt], bh[2], bh[3]);
                }
                // term hl
#pragma unroll
                for (int mt = 0; mt < 4; mt++) {
                    mma16816(acc[mt][2 * nt2],     ah[mt], bl[0], bl[1]);
                    mma16816(acc[mt][2 * nt2 + 1], ah[mt], bl[2], bl[3]);
                }
                // term lh
#pragma unroll
                for (int mt = 0; mt < 4; mt++) {
                    mma16816(acc[mt][2 * nt2],     al[mt], bh[0], bh[1]);
                    mma16816(acc[mt][2 * nt2 + 1], al[mt], bh[2], bh[3]);
                }
            }
        }
    }
#undef LOAD_STAGE

    int erow = row0 + wm + (lane >> 2);
    int ecol0 = col0 + wn + (lane & 3) * 2;
#pragma unroll
    for (int mt = 0; mt < 4; mt++) {
#pragma unroll
        for (int nt = 0; nt < 4; nt++) {
            float* c = acc[mt][nt];
            size_t r0i = (size_t)(erow + mt * 16) * N + ecol0 + nt * 8;
            *(float2*)&C[r0i]         = make_float2(c[0], c[1]);
            *(float2*)&C[r0i + 8 * N] = make_float2(c[2], c[3]);
        }
    }
}

// ---------------------------------------------------------------------------
// qkv_prep (unchanged)
// ---------------------------------------------------------------------------
__global__ __launch_bounds__(256) void qkv_prep(const float* __restrict__ qw,
                                                const float* __restrict__ kw,
                                                const float* __restrict__ cosb,
                                                const float* __restrict__ sinb)
{
    __shared__ float vt_s[64][33];
    int tid = threadIdx.x;
    int wid = tid >> 5, lane = tid & 31;
    int h = blockIdx.y;
    int t0 = blockIdx.x * 32;

#pragma unroll
    for (int j = 0; j < 4; j++) {
        int tl = wid * 4 + j;
        int t = t0 + tl;
        const float* rowbase = g_qkv + (size_t)t * (3 * DM) + h * HD;
        float2 qv = ((const float2*)rowbase)[lane];
        float2 kv = ((const float2*)(rowbase + DM))[lane];
        float2 vv = ((const float2*)(rowbase + 2 * DM))[lane];

        float sq = qv.x * qv.x + qv.y * qv.y;
        float sk = kv.x * kv.x + kv.y * kv.y;
#pragma unroll
        for (int off = 16; off; off >>= 1) {
            sq += __shfl_xor_sync(0xffffffffu, sq, off);
            sk += __shfl_xor_sync(0xffffffffu, sk, off);
        }
        float rq = rsqrtf(sq * (1.f / 64.f) + EPS_F);
        float rk = rsqrtf(sk * (1.f / 64.f) + EPS_F);

        int d0 = lane * 2;
        float q0 = qv.x * rq * qw[d0], q1 = qv.y * rq * qw[d0 + 1];
        float k0 = kv.x * rk * kw[d0], k1 = kv.y * rk * kw[d0 + 1];

        if (lane < 16) {
            float c = cosb[t * 16 + lane];
            float s = sinb[t * 16 + lane];
            float e = q0, o = q1;
            q0 = e * c - o * s;  q1 = e * s + o * c;
            e = k0; o = k1;
            k0 = e * c - o * s;  k1 = e * s + o * c;
        }
        q0 *= QSC; q1 *= QSC;

        size_t base = ((size_t)h * T_LEN + t) * HD + d0;
        uint32_t ph, pl;
        packpl(q0, q1, ph, pl);
        *(uint32_t*)&g_qs_hi[base] = ph;
        *(uint32_t*)&g_qs_lo[base] = pl;
        packpl(k0, k1, ph, pl);
        *(uint32_t*)&g_ks_hi[base] = ph;
        *(uint32_t*)&g_ks_lo[base] = pl;

        vt_s[d0][tl]     = vv.x * 0.5f;
        vt_s[d0 + 1][tl] = vv.y * 0.5f;
    }
    __syncthreads();

    int d = tid >> 2;
    int tg = (tid & 3) * 8;
    uint32_t hi[4], lo[4];
#pragma unroll
    for (int i = 0; i < 4; i++) {
        float a = vt_s[d][tg + 2 * i], b = vt_s[d][tg + 2 * i + 1];
        packpl(a, b, hi[i], lo[i]);
    }
    size_t vbase = ((size_t)h * HD + d) * T_LEN + t0 + tg;
    *(uint4*)&g_vt_hi[vbase] = make_uint4(hi[0], hi[1], hi[2], hi[3]);
    *(uint4*)&g_vt_lo[vbase] = make_uint4(lo[0], lo[1], lo[2], lo[3]);
}

// ---------------------------------------------------------------------------
// Tensor-core flash attention: 3-region smem ring (Q region joins ring),
// 1 sync/chunk, term-major MMA order, SW128 swizzle. 2 CTAs/SM.
// ---------------------------------------------------------------------------
__device__ __forceinline__ void attn_load_chunk(uint32_t dstbase, int s0,
                                                int h, int tid)
{
    int arr = tid >> 6, r = tid & 63;
    uint32_t dst = dstbase + arr * A_KARR + r * 128;
    uint32_t sw = r & 7;
    const __nv_bfloat16* src;
    if (arr == 0)      src = g_ks_hi + ((size_t)h * T_LEN + s0 + r) * HD;
    else if (arr == 1) src = g_ks_lo + ((size_t)h * T_LEN + s0 + r) * HD;
    else if (arr == 2) src = g_vt_hi + ((size_t)h * HD + r) * T_LEN + s0;
    else               src = g_vt_lo + ((size_t)h * HD + r) * T_LEN + s0;
#pragma unroll
    for (int c = 0; c < 8; c++)
        cpa16(dst + (((uint32_t)c ^ sw) << 4), (const char*)src + c * 16);
}

__global__ __launch_bounds__(256, 2) void attn_mma()
{
    uint32_t sb0 = s2u(gsm);
    int tid = threadIdx.x;
    int wid = tid >> 5, lane = tid & 31;
    int h = blockIdx.y;
    int q0 = blockIdx.x * 128;

    // Q -> region 0 (hi at 0, lo at +A_QARR), SW128
    {
        int arr = tid >> 7, r = tid & 127;
        const __nv_bfloat16* src = (arr ? g_qs_lo : g_qs_hi) +
                                   ((size_t)h * T_LEN + q0 + r) * HD;
        uint32_t dst = sb0 + arr * A_QARR + r * 128;
        uint32_t sw = r & 7;
#pragma unroll
        for (int c = 0; c < 8; c++)
            cpa16(dst + (((uint32_t)c ^ sw) << 4), (const char*)src + c * 16);
    }

    int s_begin = (q0 >= WINDOW) ? q0 - WINDOW : 0;
    int nch = (q0 + 64 - s_begin) / 64 + 1;   // >= 2 always

    attn_load_chunk(sb0 + A_STAGE, s_begin, h, tid);       // chunk0 -> region1
    CP_COMMIT();                                           // group: Q + chunk0
    attn_load_chunk(sb0 + 2 * A_STAGE, s_begin + 64, h, tid); // chunk1 -> region2
    CP_COMMIT();

    int ldsB_r = ((lane >> 4) << 3) + (lane & 7);
    uint32_t ssw = lane & 7;
    uint32_t cbit = (lane >> 3) & 1;
    int qlo_row = q0 + wid * 16 + (lane >> 2);

    CP_WAIT(1);          // Q + chunk0 done
    __syncthreads();

    // extract Q fragments (region0 then becomes a ring stage)
    uint32_t qh[4][4], ql[4][4];
    {
        int qrow = wid * 16 + (lane & 15);
        uint32_t qbase = sb0 + qrow * 128;
        uint32_t qsw = qrow & 7;
#pragma unroll
        for (int kd = 0; kd < 4; kd++) {
            uint32_t qa = qbase + ((((uint32_t)(kd * 2) + (lane >> 4)) ^ qsw) << 4);
            ldsm_x4(qh[kd][0], qh[kd][1], qh[kd][2], qh[kd][3], qa);
            ldsm_x4(ql[kd][0], ql[kd][1], ql[kd][2], ql[kd][3], qa + A_QARR);
        }
    }

    float m0 = -1e30f, m1 = -1e30f, l0 = 0.f, l1 = 0.f;
    float O[8][4] = {};

    for (int i = 0; i < nch; i++) {
        int s0 = s_begin + i * 64;
        uint32_t stb = sb0 + ((i + 1) % 3) * A_STAGE;
        CP_WAIT(1);
        __syncthreads();
        if (i + 2 < nch)
            attn_load_chunk(sb0 + ((i + 3) % 3) * A_STAGE, s0 + 128, h, tid);
        CP_COMMIT();

        // ---- S = Q @ K^T (term-major 3-term) ----
        float S[8][4] = {};
#pragma unroll
        for (int kd = 0; kd < 4; kd++) {
            uint32_t kcsw = (((uint32_t)(kd * 2) + cbit) ^ ssw) << 4;
#pragma unroll
            for (int p = 0; p < 2; p++) {
                uint32_t bh[2][4], bl[2][4];
#pragma unroll
                for (int j = 0; j < 2; j++) {
                    uint32_t ka = stb + ((2 * p + j) * 16 + ldsB_r) * 128 + kcsw;
                    ldsm_x4(bh[j][0], bh[j][1], bh[j][2], bh[j][3], ka);
                    ldsm_x4(bl[j][0], bl[j][1], bl[j][2], bl[j][3], ka + A_KARR);
                }
#pragma unroll
                for (int j = 0; j < 2; j++) {
                    mma16816(S[2 * (2 * p + j)],     qh[kd], bh[j][0], bh[j][1]);
                    mma16816(S[2 * (2 * p + j) + 1], qh[kd], bh[j][2], bh[j][3]);
                }
#pragma unroll
                for (int j = 0; j < 2; j++) {
                    mma16816(S[2 * (2 * p + j)],     qh[kd], bl[j][0], bl[j][1]);
                    mma16816(S[2 * (2 * p + j) + 1], qh[kd], bl[j][2], bl[j][3]);
                }
#pragma unroll
                for (int j = 0; j < 2; j++) {
                    mma16816(S[2 * (2 * p + j)],     ql[kd], bh[j][0], bh[j][1]);
                    mma16816(S[2 * (2 * p + j) + 1], ql[kd], bh[j][2], bh[j][3]);
                }
            }
        }

        // ---- mask (boundary chunks only) ----
        if ((s0 + 63 > q0) || (q0 + 127 - s0 >= WINDOW)) {
#pragma unroll
            for (int nt = 0; nt < 8; nt++) {
                int sc = s0 + nt * 8 + (lane & 3) * 2;
#pragma unroll
                for (int e = 0; e < 2; e++) {
                    int d1 = qlo_row - (sc + e);
                    int d2 = d1 + 8;
                    if (d1 < 0 || d1 >= WINDOW) S[nt][e] = -1e30f;
                    if (d2 < 0 || d2 >= WINDOW) S[nt][2 + e] = -1e30f;
                }
            }
        }

        // ---- online softmax (log2 space) ----
        float r0 = -1e30f, r1 = -1e30f;
#pragma unroll
        for (int nt = 0; nt < 8; nt++) {
            r0 = fmaxf(r0, fmaxf(S[nt][0], S[nt][1]));
            r1 = fmaxf(r1, fmaxf(S[nt][2], S[nt][3]));
        }
        r0 = fmaxf(r0, __shfl_xor_sync(0xffffffffu, r0, 1));
        r0 = fmaxf(r0, __shfl_xor_sync(0xffffffffu, r0, 2));
        r1 = fmaxf(r1, __shfl_xor_sync(0xffffffffu, r1, 1));
        r1 = fmaxf(r1, __shfl_xor_sync(0xffffffffu, r1, 2));
        float mn0 = fmaxf(m0, r0), mn1 = fmaxf(m1, r1);
        float al0 = fex2(m0 - mn0), al1 = fex2(m1 - mn1);
        m0 = mn0; m1 = mn1;
        float ps0 = 0.f, ps1 = 0.f;
#pragma unroll
        for (int nt = 0; nt < 8; nt++) {
            S[nt][0] = fex2(S[nt][0] - mn0);
            S[nt][1] = fex2(S[nt][1] - mn0);
            S[nt][2] = fex2(S[nt][2] - mn1);
            S[nt][3] = fex2(S[nt][3] - mn1);
            ps0 += S[nt][0] + S[nt][1];
            ps1 += S[nt][2] + S[nt][3];
        }
        ps0 += __shfl_xor_sync(0xffffffffu, ps0, 1);
        ps0 += __shfl_xor_sync(0xffffffffu, ps0, 2);
        ps1 += __shfl_xor_sync(0xffffffffu, ps1, 1);
        ps1 += __shfl_xor_sync(0xffffffffu, ps1, 2);
        l0 = l0 * al0 + ps0;
        l1 = l1 * al1 + ps1;
#pragma unroll
        for (int nt = 0; nt < 8; nt++) {
            O[nt][0] *= al0; O[nt][1] *= al0;
            O[nt][2] *= al1; O[nt][3] *= al1;
        }

        // ---- O += P @ V (term-major 3-term; P split exactly) ----
#pragma unroll
        for (int kc = 0; kc < 4; kc++) {
            uint32_t pa[4], pl[4];
            packpl(S[2 * kc][0],     S[2 * kc][1],     pa[0], pl[0]);
            packpl(S[2 * kc][2],     S[2 * kc][3],     pa[1], pl[1]);
            packpl(S[2 * kc + 1][0], S[2 * kc + 1][1], pa[2], pl[2]);
            packpl(S[2 * kc + 1][2], S[2 * kc + 1][3], pa[3], pl[3]);
            uint32_t vcsw = (((uint32_t)(kc * 2) + cbit) ^ ssw) << 4;
#pragma unroll
            for (int p = 0; p < 2; p++) {
                uint32_t vh[2][4], vl[2][4];
#pragma unroll
                for (int j = 0; j < 2; j++) {
                    uint32_t va = stb + 2 * A_KARR +
                                  ((2 * p + j) * 16 + ldsB_r) * 128 + vcsw;
                    ldsm_x4(vh[j][0], vh[j][1], vh[j][2], vh[j][3], va);
                    ldsm_x4(vl[j][0], vl[j][1], vl[j][2], vl[j][3], va + A_KARR);
                }
#pragma unroll
                for (int j = 0; j < 2; j++) {
                    mma16816(O[2 * (2 * p + j)],     pa, vh[j][0], vh[j][1]);
                    mma16816(O[2 * (2 * p + j) + 1], pa, vh[j][2], vh[j][3]);
                }
#pragma unroll
                for (int j = 0; j < 2; j++) {
                    mma16816(O[2 * (2 * p + j)],     pa, vl[j][0], vl[j][1]);
                    mma16816(O[2 * (2 * p + j) + 1], pa, vl[j][2], vl[j][3]);
                }
#pragma unroll
                for (int j = 0; j < 2; j++) {
                    mma16816(O[2 * (2 * p + j)],     pl, vh[j][0], vh[j][1]);
                    mma16816(O[2 * (2 * p + j) + 1], pl, vh[j][2], vh[j][3]);
                }
            }
        }
    }

    // ---- epilogue ----
    float i0 = 1.f / l0, i1 = 1.f / l1;
    int colb = h * HD + (lane & 3) * 2;
#pragma unroll
    for (int nt = 0; nt < 8; nt++) {
        size_t b0 = (size_t)qlo_row * DM + colb + nt * 8;
        size_t b1 = (size_t)(qlo_row + 8) * DM + colb + nt * 8;
        float v0 = O[nt][0] * i0, v1 = O[nt][1] * i0;
        float v2 = O[nt][2] * i1, v3 = O[nt][3] * i1;
        uint32_t ph, pl;
        packpl(v0, v1, ph, pl);
        *(uint32_t*)&g_att_hi[b0] = ph;
        *(uint32_t*)&g_att_lo[b0] = pl;
        packpl(v2, v3, ph, pl);
        *(uint32_t*)&g_att_hi[b1] = ph;
        *(uint32_t*)&g_att_lo[b1] = pl;
    }
}

// ---------------------------------------------------------------------------
extern "C" void kernel_launch(void* const* d_in, const int* in_sizes, int n_in,
                              void* d_out, int out_size)
{
    const float* x     = (const float*)d_in[0];
    const float* w_qkv = (const float*)d_in[3];
    const float* w_o   = (const float*)d_in[4];
    const float* qw    = (const float*)d_in[5];
    const float* kw    = (const float*)d_in[6];
    const float* cosb  = (const float*)d_in[7];
    const float* sinb  = (const float*)d_in[8];
    float* out = (float*)d_out;

    float* qkv_p = nullptr;
    __nv_bfloat16 *xh, *xl, *wqh, *wql, *woh, *wol, *ath, *atl;
    cudaGetSymbolAddress((void**)&qkv_p, g_qkv);
    cudaGetSymbolAddress((void**)&xh, g_x_hi);
    cudaGetSymbolAddress((void**)&xl, g_x_lo);
    cudaGetSymbolAddress((void**)&wqh, g_wqkv_hi);
    cudaGetSymbolAddress((void**)&wql, g_wqkv_lo);
    cudaGetSymbolAddress((void**)&woh, g_wo_hi);
    cudaGetSymbolAddress((void**)&wol, g_wo_lo);
    cudaGetSymbolAddress((void**)&ath, g_att_hi);
    cudaGetSymbolAddress((void**)&atl, g_att_lo);

    static bool attr_done = false;
    if (!attr_done) {
        cudaFuncSetAttribute(gemm_mma, cudaFuncAttributeMaxDynamicSharedMemorySize, G_SMEM);
        cudaFuncSetAttribute(attn_mma, cudaFuncAttributeMaxDynamicSharedMemorySize, A_SMEM);
        attr_done = true;
    }

    // 0) split inputs to bf16 hi/lo
    cvt_hilo<<<(T_LEN * DM / 4 + 255) / 256, 256>>>(x, xh, xl, T_LEN * DM / 4);
    cvt_hilo<<<(3 * DM * DM / 4 + 255) / 256, 256>>>(w_qkv, wqh, wql, 3 * DM * DM / 4);
    cvt_hilo<<<(DM * DM / 4 + 255) / 256, 256>>>(w_o, woh, wol, DM * DM / 4);

    // 1) qkv = x @ w_qkv^T
    dim3 g1(3 * DM / BN, T_LEN / BM);
    gemm_mma<<<g1, 256, G_SMEM>>>(xh, xl, wqh, wql, qkv_p, T_LEN, 3 * DM, DM);

    // 2) norm + rope + v-scale, emit bf16 hi/lo
    dim3 gp(T_LEN / 32, NH);
    qkv_prep<<<gp, 256>>>(qw, kw, cosb, sinb);

    // 3) tensor-core windowed attention -> att (bf16 hi/lo)
    dim3 ga(T_LEN / 128, NH);
    attn_mma<<<ga, 256, A_SMEM>>>();

    // 4) out = att @ w_o^T
    dim3 g2(DM / BN, T_LEN / BM);
    gemm_mma<<<g2, 256, G_SMEM>>>(ath, atl, woh, wol, out, T_LEN, DM, DM);
}

// round 15
// speedup vs baseline: 9.4496x; 1.2292x over previous
#include <cuda_runtime.h>
#include <cuda_fp16.h>
#include <math.h>
#include <stdint.h>

#define T_LEN 4096
#define DM 1024
#define NH 16
#define HD 64
#define WINDOW 1024
#define EPS_F 1e-6f
#define QSC 0.17312340490667564f   // 0.12 * log2(e)

// GEMM tiling: 128x128, BK=32, 64B rows, swizzle chunk^=(row>>1)&3
// 2-term fp16: C = A*(Bhi+Blo); arrays: A, Bhi, Blo
#define BM 128
#define BN 128
#define BK 32
#define G_ARR 8192                  // 128 rows * 64 B
#define G_STAGE 24576               // 3 arrays
#define G_SMEM (3 * G_STAGE)        // 73728

// Attention: 128B rows, SW128 swizzle chunk^=row&7 (3-term fp16)
#define A_KARR 8192                 // 64 rows * 128 B
#define A_STAGE 32768               // Khi Klo Vhi Vlo
#define A_QARR 16384                // 128 rows * 128 B
#define A_SMEM (3 * A_STAGE)        // 98304

// ------------------------- scratch (no allocs allowed) ----------------------
__device__ float g_qkv[(size_t)T_LEN * 3 * DM];
__device__ __half g_x[(size_t)T_LEN * DM];
__device__ __half g_wqkv_hi[(size_t)3 * DM * DM];
__device__ __half g_wqkv_lo[(size_t)3 * DM * DM];
__device__ __half g_wo_hi[(size_t)DM * DM];
__device__ __half g_wo_lo[(size_t)DM * DM];
__device__ __half g_att[(size_t)T_LEN * DM];
__device__ __half g_qs_hi[(size_t)NH * T_LEN * HD];
__device__ __half g_qs_lo[(size_t)NH * T_LEN * HD];
__device__ __half g_ks_hi[(size_t)NH * T_LEN * HD];
__device__ __half g_ks_lo[(size_t)NH * T_LEN * HD];
__device__ __half g_vt_hi[(size_t)NH * HD * T_LEN];
__device__ __half g_vt_lo[(size_t)NH * HD * T_LEN];

// ------------------------- helpers ------------------------------------------
__device__ __forceinline__ uint32_t s2u(const void* p) {
    uint32_t a;
    asm("{ .reg .u64 t; cvta.to.shared.u64 t, %1; cvt.u32.u64 %0, t; }"
        : "=r"(a) : "l"(p));
    return a;
}
__device__ __forceinline__ void cpa16(uint32_t dst, const void* src) {
    asm volatile("cp.async.cg.shared.global [%0], [%1], 16;" :: "r"(dst), "l"(src));
}
#define CP_COMMIT() asm volatile("cp.async.commit_group;" ::: "memory")
#define CP_WAIT(n)  asm volatile("cp.async.wait_group %0;" :: "n"(n) : "memory")
__device__ __forceinline__ void ldsm_x4(uint32_t& r0, uint32_t& r1,
                                        uint32_t& r2, uint32_t& r3, uint32_t a) {
    asm volatile("ldmatrix.sync.aligned.m8n8.x4.shared.b16 {%0,%1,%2,%3}, [%4];"
                 : "=r"(r0), "=r"(r1), "=r"(r2), "=r"(r3) : "r"(a));
}
__device__ __forceinline__ void mma16816(float* c, const uint32_t* a,
                                         uint32_t b0, uint32_t b1) {
    asm volatile(
        "mma.sync.aligned.m16n8k16.row.col.f32.f16.f16.f32 "
        "{%0,%1,%2,%3}, {%4,%5,%6,%7}, {%8,%9}, {%0,%1,%2,%3};"
        : "+f"(c[0]), "+f"(c[1]), "+f"(c[2]), "+f"(c[3])
        : "r"(a[0]), "r"(a[1]), "r"(a[2]), "r"(a[3]), "r"(b0), "r"(b1));
}
__device__ __forceinline__ float fex2(float x) {
    float y;
    asm("ex2.approx.ftz.f32 %0, %1;" : "=f"(y) : "f"(x));
    return y;
}
__device__ __forceinline__ uint32_t packh2(float a, float b) {
    __half2 p = __halves2half2(__float2half(a), __float2half(b));
    return *(uint32_t*)&p;
}
__device__ __forceinline__ void packpl(float p0, float p1, uint32_t& hi, uint32_t& lo) {
    __half h0 = __float2half(p0), h1 = __float2half(p1);
    __half2 hp = __halves2half2(h0, h1);
    hi = *(uint32_t*)&hp;
    __half2 lp = __halves2half2(__float2half(p0 - __half2float(h0)),
                                __float2half(p1 - __half2float(h1)));
    lo = *(uint32_t*)&lp;
}

// ---------------------------------------------------------------------------
// fp32 -> fp16 (1-term, for x)
// ---------------------------------------------------------------------------
__global__ __launch_bounds__(256) void cvt_h1(const float* __restrict__ in,
                                              __half* __restrict__ out, int n4)
{
    int i = blockIdx.x * 256 + threadIdx.x;
    if (i >= n4) return;
    float4 v = ((const float4*)in)[i];
    ((uint32_t*)out)[2 * i]     = packh2(v.x, v.y);
    ((uint32_t*)out)[2 * i + 1] = packh2(v.z, v.w);
}

// fp32 -> (fp16 hi, fp16 lo) split (for weights)
__global__ __launch_bounds__(256) void cvt_h2(const float* __restrict__ in,
                                              __half* __restrict__ hi,
                                              __half* __restrict__ lo, int n4)
{
    int i = blockIdx.x * 256 + threadIdx.x;
    if (i >= n4) return;
    float4 v = ((const float4*)in)[i];
    uint32_t h0, l0, h1, l1;
    packpl(v.x, v.y, h0, l0);
    packpl(v.z, v.w, h1, l1);
    ((uint32_t*)hi)[2 * i]     = h0;
    ((uint32_t*)hi)[2 * i + 1] = h1;
    ((uint32_t*)lo)[2 * i]     = l0;
    ((uint32_t*)lo)[2 * i + 1] = l1;
}

// ---------------------------------------------------------------------------
// mma.sync GEMM: C = A @ (Bhi+Blo)^T, fp16 2-term. 3-stage pipeline,
// term-major, swizzled 64B-row smem, 2 CTAs/SM.
// ---------------------------------------------------------------------------
extern __shared__ __align__(128) char gsm[];

__global__ __launch_bounds__(256, 2) void gemm_mma(const __half* __restrict__ A,
                                                   const __half* __restrict__ Bhi,
                                                   const __half* __restrict__ Blo,
                                                   float* __restrict__ C,
                                                   int M, int N, int K)
{
    uint32_t sbase = s2u(gsm);
    int tid = threadIdx.x;
    int wid = tid >> 5;
    int lane = tid & 31;
    int wm = (wid >> 2) * 64;
    int wn = (wid & 3) * 32;
    int row0 = blockIdx.y * BM;
    int col0 = blockIdx.x * BN;

    int lrow = tid >> 2;
    int lkc = tid & 3;
    const char* gA  = (const char*)(A   + (size_t)(row0 + lrow) * K + lkc * 8);
    const char* gBh = (const char*)(Bhi + (size_t)(col0 + lrow) * K + lkc * 8);
    const char* gBl = (const char*)(Blo + (size_t)(col0 + lrow) * K + lkc * 8);
    size_t gstep = (size_t)64 * K * 2;
    uint32_t sw0 = lrow * 64 + ((lkc ^ ((lrow >> 1) & 3)) << 4);
    uint32_t sw1 = sw0 + 64 * 64;

#define LOAD_STAGE(st, k0)                                                  \
    do {                                                                    \
        uint32_t sb = sbase + (st) * G_STAGE;                               \
        size_t go = (size_t)(k0) * 2;                                       \
        cpa16(sb + sw0,             gA + go);                               \
        cpa16(sb + sw1,             gA + go + gstep);                       \
        cpa16(sb + G_ARR + sw0,     gBh + go);                              \
        cpa16(sb + G_ARR + sw1,     gBh + go + gstep);                      \
        cpa16(sb + 2 * G_ARR + sw0, gBl + go);                              \
        cpa16(sb + 2 * G_ARR + sw1, gBl + go + gstep);                      \
    } while (0)

    float acc[4][4][4] = {};

    int a_r = wm + (lane & 15);
    uint32_t s_a = ((lane & 15) >> 1) & 3;
    int b_r = wn + ((lane >> 4) << 3) + (lane & 7);
    uint32_t s_b = (((((lane >> 4) << 3) + (lane & 7))) >> 1) & 3;
    uint32_t a_cb = lane >> 4;
    uint32_t b_cb = (lane >> 3) & 1;

    LOAD_STAGE(0, 0);
    CP_COMMIT();
    LOAD_STAGE(1, BK);
    CP_COMMIT();

    const int NKT = K / BK;
    for (int kt = 0; kt < NKT; kt++) {
        CP_WAIT(1);
        __syncthreads();
        if (kt + 2 < NKT) LOAD_STAGE((kt + 2) % 3, (kt + 2) * BK);
        CP_COMMIT();

        uint32_t stb = sbase + (kt % 3) * G_STAGE;
#pragma unroll
        for (int ks = 0; ks < 2; ks++) {
            uint32_t ah[4][4];
            uint32_t acsw = ((ks * 2 + a_cb) ^ s_a) << 4;
#pragma unroll
            for (int mt = 0; mt < 4; mt++) {
                uint32_t aaddr = stb + (a_r + mt * 16) * 64 + acsw;
                ldsm_x4(ah[mt][0], ah[mt][1], ah[mt][2], ah[mt][3], aaddr);
            }
            uint32_t bcsw = ((ks * 2 + b_cb) ^ s_b) << 4;
#pragma unroll
            for (int nt2 = 0; nt2 < 2; nt2++) {
                uint32_t bh[4], bl[4];
                uint32_t baddr = stb + G_ARR + (b_r + nt2 * 16) * 64 + bcsw;
                ldsm_x4(bh[0], bh[1], bh[2], bh[3], baddr);
                ldsm_x4(bl[0], bl[1], bl[2], bl[3], baddr + G_ARR);
                // term A*Bhi
#pragma unroll
                for (int mt = 0; mt < 4; mt++) {
                    mma16816(acc[mt][2 * nt2],     ah[mt], bh[0], bh[1]);
                    mma16816(acc[mt][2 * nt2 + 1], ah[mt], bh[2], bh[3]);
                }
                // term A*Blo
#pragma unroll
                for (int mt = 0; mt < 4; mt++) {
                    mma16816(acc[mt][2 * nt2],     ah[mt], bl[0], bl[1]);
                    mma16816(acc[mt][2 * nt2 + 1], ah[mt], bl[2], bl[3]);
                }
            }
        }
    }
#undef LOAD_STAGE

    int erow = row0 + wm + (lane >> 2);
    int ecol0 = col0 + wn + (lane & 3) * 2;
#pragma unroll
    for (int mt = 0; mt < 4; mt++) {
#pragma unroll
        for (int nt = 0; nt < 4; nt++) {
            float* c = acc[mt][nt];
            size_t r0i = (size_t)(erow + mt * 16) * N + ecol0 + nt * 8;
            *(float2*)&C[r0i]         = make_float2(c[0], c[1]);
            *(float2*)&C[r0i + 8 * N] = make_float2(c[2], c[3]);
        }
    }
}

// ---------------------------------------------------------------------------
// qkv_prep: RMSNorm q,k + RoPE + v*0.5, fp16 hi/lo outputs
// ---------------------------------------------------------------------------
__global__ __launch_bounds__(256) void qkv_prep(const float* __restrict__ qw,
                                                const float* __restrict__ kw,
                                                const float* __restrict__ cosb,
                                                const float* __restrict__ sinb)
{
    __shared__ float vt_s[64][33];
    int tid = threadIdx.x;
    int wid = tid >> 5, lane = tid & 31;
    int h = blockIdx.y;
    int t0 = blockIdx.x * 32;

#pragma unroll
    for (int j = 0; j < 4; j++) {
        int tl = wid * 4 + j;
        int t = t0 + tl;
        const float* rowbase = g_qkv + (size_t)t * (3 * DM) + h * HD;
        float2 qv = ((const float2*)rowbase)[lane];
        float2 kv = ((const float2*)(rowbase + DM))[lane];
        float2 vv = ((const float2*)(rowbase + 2 * DM))[lane];

        float sq = qv.x * qv.x + qv.y * qv.y;
        float sk = kv.x * kv.x + kv.y * kv.y;
#pragma unroll
        for (int off = 16; off; off >>= 1) {
            sq += __shfl_xor_sync(0xffffffffu, sq, off);
            sk += __shfl_xor_sync(0xffffffffu, sk, off);
        }
        float rq = rsqrtf(sq * (1.f / 64.f) + EPS_F);
        float rk = rsqrtf(sk * (1.f / 64.f) + EPS_F);

        int d0 = lane * 2;
        float q0 = qv.x * rq * qw[d0], q1 = qv.y * rq * qw[d0 + 1];
        float k0 = kv.x * rk * kw[d0], k1 = kv.y * rk * kw[d0 + 1];

        if (lane < 16) {
            float c = cosb[t * 16 + lane];
            float s = sinb[t * 16 + lane];
            float e = q0, o = q1;
            q0 = e * c - o * s;  q1 = e * s + o * c;
            e = k0; o = k1;
            k0 = e * c - o * s;  k1 = e * s + o * c;
        }
        q0 *= QSC; q1 *= QSC;

        size_t base = ((size_t)h * T_LEN + t) * HD + d0;
        uint32_t ph, pl;
        packpl(q0, q1, ph, pl);
        *(uint32_t*)&g_qs_hi[base] = ph;
        *(uint32_t*)&g_qs_lo[base] = pl;
        packpl(k0, k1, ph, pl);
        *(uint32_t*)&g_ks_hi[base] = ph;
        *(uint32_t*)&g_ks_lo[base] = pl;

        vt_s[d0][tl]     = vv.x * 0.5f;
        vt_s[d0 + 1][tl] = vv.y * 0.5f;
    }
    __syncthreads();

    int d = tid >> 2;
    int tg = (tid & 3) * 8;
    uint32_t hi[4], lo[4];
#pragma unroll
    for (int i = 0; i < 4; i++) {
        float a = vt_s[d][tg + 2 * i], b = vt_s[d][tg + 2 * i + 1];
        packpl(a, b, hi[i], lo[i]);
    }
    size_t vbase = ((size_t)h * HD + d) * T_LEN + t0 + tg;
    *(uint4*)&g_vt_hi[vbase] = make_uint4(hi[0], hi[1], hi[2], hi[3]);
    *(uint4*)&g_vt_lo[vbase] = make_uint4(lo[0], lo[1], lo[2], lo[3]);
}

// ---------------------------------------------------------------------------
// Tensor-core flash attention: fp16 3-term, 3-region smem ring, 2 CTAs/SM.
// ---------------------------------------------------------------------------
__device__ __forceinline__ void attn_load_chunk(uint32_t dstbase, int s0,
                                                int h, int tid)
{
    int arr = tid >> 6, r = tid & 63;
    uint32_t dst = dstbase + arr * A_KARR + r * 128;
    uint32_t sw = r & 7;
    const __half* src;
    if (arr == 0)      src = g_ks_hi + ((size_t)h * T_LEN + s0 + r) * HD;
    else if (arr == 1) src = g_ks_lo + ((size_t)h * T_LEN + s0 + r) * HD;
    else if (arr == 2) src = g_vt_hi + ((size_t)h * HD + r) * T_LEN + s0;
    else               src = g_vt_lo + ((size_t)h * HD + r) * T_LEN + s0;
#pragma unroll
    for (int c = 0; c < 8; c++)
        cpa16(dst + (((uint32_t)c ^ sw) << 4), (const char*)src + c * 16);
}

__global__ __launch_bounds__(256, 2) void attn_mma()
{
    uint32_t sb0 = s2u(gsm);
    int tid = threadIdx.x;
    int wid = tid >> 5, lane = tid & 31;
    int h = blockIdx.y;
    int q0 = blockIdx.x * 128;

    // Q -> region 0 (hi at 0, lo at +A_QARR), SW128
    {
        int arr = tid >> 7, r = tid & 127;
        const __half* src = (arr ? g_qs_lo : g_qs_hi) +
                            ((size_t)h * T_LEN + q0 + r) * HD;
        uint32_t dst = sb0 + arr * A_QARR + r * 128;
        uint32_t sw = r & 7;
#pragma unroll
        for (int c = 0; c < 8; c++)
            cpa16(dst + (((uint32_t)c ^ sw) << 4), (const char*)src + c * 16);
    }

    int s_begin = (q0 >= WINDOW) ? q0 - WINDOW : 0;
    int nch = (q0 + 64 - s_begin) / 64 + 1;

    attn_load_chunk(sb0 + A_STAGE, s_begin, h, tid);
    CP_COMMIT();
    attn_load_chunk(sb0 + 2 * A_STAGE, s_begin + 64, h, tid);
    CP_COMMIT();

    int ldsB_r = ((lane >> 4) << 3) + (lane & 7);
    uint32_t ssw = lane & 7;
    uint32_t cbit = (lane >> 3) & 1;
    int qlo_row = q0 + wid * 16 + (lane >> 2);

    CP_WAIT(1);
    __syncthreads();

    uint32_t qh[4][4], ql[4][4];
    {
        int qrow = wid * 16 + (lane & 15);
        uint32_t qbase = sb0 + qrow * 128;
        uint32_t qsw = qrow & 7;
#pragma unroll
        for (int kd = 0; kd < 4; kd++) {
            uint32_t qa = qbase + ((((uint32_t)(kd * 2) + (lane >> 4)) ^ qsw) << 4);
            ldsm_x4(qh[kd][0], qh[kd][1], qh[kd][2], qh[kd][3], qa);
            ldsm_x4(ql[kd][0], ql[kd][1], ql[kd][2], ql[kd][3], qa + A_QARR);
        }
    }

    float m0 = -1e30f, m1 = -1e30f, l0 = 0.f, l1 = 0.f;
    float O[8][4] = {};

    for (int i = 0; i < nch; i++) {
        int s0 = s_begin + i * 64;
        uint32_t stb = sb0 + ((i + 1) % 3) * A_STAGE;
        CP_WAIT(1);
        __syncthreads();
        if (i + 2 < nch)
            attn_load_chunk(sb0 + ((i + 3) % 3) * A_STAGE, s0 + 128, h, tid);
        CP_COMMIT();

        // ---- S = Q @ K^T (term-major 3-term) ----
        float S[8][4] = {};
#pragma unroll
        for (int kd = 0; kd < 4; kd++) {
            uint32_t kcsw = (((uint32_t)(kd * 2) + cbit) ^ ssw) << 4;
#pragma unroll
            for (int p = 0; p < 2; p++) {
                uint32_t bh[2][4], bl[2][4];
#pragma unroll
                for (int j = 0; j < 2; j++) {
                    uint32_t ka = stb + ((2 * p + j) * 16 + ldsB_r) * 128 + kcsw;
                    ldsm_x4(bh[j][0], bh[j][1], bh[j][2], bh[j][3], ka);
                    ldsm_x4(bl[j][0], bl[j][1], bl[j][2], bl[j][3], ka + A_KARR);
                }
#pragma unroll
                for (int j = 0; j < 2; j++) {
                    mma16816(S[2 * (2 * p + j)],     qh[kd], bh[j][0], bh[j][1]);
                    mma16816(S[2 * (2 * p + j) + 1], qh[kd], bh[j][2], bh[j][3]);
                }
#pragma unroll
                for (int j = 0; j < 2; j++) {
                    mma16816(S[2 * (2 * p + j)],     qh[kd], bl[j][0], bl[j][1]);
                    mma16816(S[2 * (2 * p + j) + 1], qh[kd], bl[j][2], bl[j][3]);
                }
#pragma unroll
                for (int j = 0; j < 2; j++) {
                    mma16816(S[2 * (2 * p + j)],     ql[kd], bh[j][0], bh[j][1]);
                    mma16816(S[2 * (2 * p + j) + 1], ql[kd], bh[j][2], bh[j][3]);
                }
            }
        }

        // ---- mask (boundary chunks only) ----
        if ((s0 + 63 > q0) || (q0 + 127 - s0 >= WINDOW)) {
#pragma unroll
            for (int nt = 0; nt < 8; nt++) {
                int sc = s0 + nt * 8 + (lane & 3) * 2;
#pragma unroll
                for (int e = 0; e < 2; e++) {
                    int d1 = qlo_row - (sc + e);
                    int d2 = d1 + 8;
                    if (d1 < 0 || d1 >= WINDOW) S[nt][e] = -1e30f;
                    if (d2 < 0 || d2 >= WINDOW) S[nt][2 + e] = -1e30f;
                }
            }
        }

        // ---- online softmax (log2 space) ----
        float r0 = -1e30f, r1 = -1e30f;
#pragma unroll
        for (int nt = 0; nt < 8; nt++) {
            r0 = fmaxf(r0, fmaxf(S[nt][0], S[nt][1]));
            r1 = fmaxf(r1, fmaxf(S[nt][2], S[nt][3]));
        }
        r0 = fmaxf(r0, __shfl_xor_sync(0xffffffffu, r0, 1));
        r0 = fmaxf(r0, __shfl_xor_sync(0xffffffffu, r0, 2));
        r1 = fmaxf(r1, __shfl_xor_sync(0xffffffffu, r1, 1));
        r1 = fmaxf(r1, __shfl_xor_sync(0xffffffffu, r1, 2));
        float mn0 = fmaxf(m0, r0), mn1 = fmaxf(m1, r1);
        float al0 = fex2(m0 - mn0), al1 = fex2(m1 - mn1);
        m0 = mn0; m1 = mn1;
        float ps0 = 0.f, ps1 = 0.f;
#pragma unroll
        for (int nt = 0; nt < 8; nt++) {
            S[nt][0] = fex2(S[nt][0] - mn0);
            S[nt][1] = fex2(S[nt][1] - mn0);
            S[nt][2] = fex2(S[nt][2] - mn1);
            S[nt][3] = fex2(S[nt][3] - mn1);
            ps0 += S[nt][0] + S[nt][1];
            ps1 += S[nt][2] + S[nt][3];
        }
        ps0 += __shfl_xor_sync(0xffffffffu, ps0, 1);
        ps0 += __shfl_xor_sync(0xffffffffu, ps0, 2);
        ps1 += __shfl_xor_sync(0xffffffffu, ps1, 1);
        ps1 += __shfl_xor_sync(0xffffffffu, ps1, 2);
        l0 = l0 * al0 + ps0;
        l1 = l1 * al1 + ps1;
#pragma unroll
        for (int nt = 0; nt < 8; nt++) {
            O[nt][0] *= al0; O[nt][1] *= al0;
            O[nt][2] *= al1; O[nt][3] *= al1;
        }

        // ---- O += P @ V (term-major 3-term; P split exactly) ----
#pragma unroll
        for (int kc = 0; kc < 4; kc++) {
            uint32_t pa[4], pl[4];
            packpl(S[2 * kc][0],     S[2 * kc][1],     pa[0], pl[0]);
            packpl(S[2 * kc][2],     S[2 * kc][3],     pa[1], pl[1]);
            packpl(S[2 * kc + 1][0], S[2 * kc + 1][1], pa[2], pl[2]);
            packpl(S[2 * kc + 1][2], S[2 * kc + 1][3], pa[3], pl[3]);
            uint32_t vcsw = (((uint32_t)(kc * 2) + cbit) ^ ssw) << 4;
#pragma unroll
            for (int p = 0; p < 2; p++) {
                uint32_t vh[2][4], vl[2][4];
#pragma unroll
                for (int j = 0; j < 2; j++) {
                    uint32_t va = stb + 2 * A_KARR +
                                  ((2 * p + j) * 16 + ldsB_r) * 128 + vcsw;
                    ldsm_x4(vh[j][0], vh[j][1], vh[j][2], vh[j][3], va);
                    ldsm_x4(vl[j][0], vl[j][1], vl[j][2], vl[j][3], va + A_KARR);
                }
#pragma unroll
                for (int j = 0; j < 2; j++) {
                    mma16816(O[2 * (2 * p + j)],     pa, vh[j][0], vh[j][1]);
                    mma16816(O[2 * (2 * p + j) + 1], pa, vh[j][2], vh[j][3]);
                }
#pragma unroll
                for (int j = 0; j < 2; j++) {
                    mma16816(O[2 * (2 * p + j)],     pa, vl[j][0], vl[j][1]);
                    mma16816(O[2 * (2 * p + j) + 1], pa, vl[j][2], vl[j][3]);
                }
#pragma unroll
                for (int j = 0; j < 2; j++) {
                    mma16816(O[2 * (2 * p + j)],     pl, vh[j][0], vh[j][1]);
                    mma16816(O[2 * (2 * p + j) + 1], pl, vh[j][2], vh[j][3]);
                }
            }
        }
    }

    // ---- epilogue: normalize, write att as fp16 (gemm2 A operand) ----
    float i0 = 1.f / l0, i1 = 1.f / l1;
    int colb = h * HD + (lane & 3) * 2;
#pragma unroll
    for (int nt = 0; nt < 8; nt++) {
        size_t b0 = (size_t)qlo_row * DM + colb + nt * 8;
        size_t b1 = (size_t)(qlo_row + 8) * DM + colb + nt * 8;
        *(uint32_t*)&g_att[b0] = packh2(O[nt][0] * i0, O[nt][1] * i0);
        *(uint32_t*)&g_att[b1] = packh2(O[nt][2] * i1, O[nt][3] * i1);
    }
}

// ---------------------------------------------------------------------------
extern "C" void kernel_launch(void* const* d_in, const int* in_sizes, int n_in,
                              void* d_out, int out_size)
{
    const float* x     = (const float*)d_in[0];
    const float* w_qkv = (const float*)d_in[3];
    const float* w_o   = (const float*)d_in[4];
    const float* qw    = (const float*)d_in[5];
    const float* kw    = (const float*)d_in[6];
    const float* cosb  = (const float*)d_in[7];
    const float* sinb  = (const float*)d_in[8];
    float* out = (float*)d_out;

    float* qkv_p = nullptr;
    __half *xp, *wqh, *wql, *woh, *wol, *atp;
    cudaGetSymbolAddress((void**)&qkv_p, g_qkv);
    cudaGetSymbolAddress((void**)&xp, g_x);
    cudaGetSymbolAddress((void**)&wqh, g_wqkv_hi);
    cudaGetSymbolAddress((void**)&wql, g_wqkv_lo);
    cudaGetSymbolAddress((void**)&woh, g_wo_hi);
    cudaGetSymbolAddress((void**)&wol, g_wo_lo);
    cudaGetSymbolAddress((void**)&atp, g_att);

    static bool attr_done = false;
    if (!attr_done) {
        cudaFuncSetAttribute(gemm_mma, cudaFuncAttributeMaxDynamicSharedMemorySize, G_SMEM);
        cudaFuncSetAttribute(attn_mma, cudaFuncAttributeMaxDynamicSharedMemorySize, A_SMEM);
        attr_done = true;
    }

    // 0) converts
    cvt_h1<<<(T_LEN * DM / 4 + 255) / 256, 256>>>(x, xp, T_LEN * DM / 4);
    cvt_h2<<<(3 * DM * DM / 4 + 255) / 256, 256>>>(w_qkv, wqh, wql, 3 * DM * DM / 4);
    cvt_h2<<<(DM * DM / 4 + 255) / 256, 256>>>(w_o, woh, wol, DM * DM / 4);

    // 1) qkv = x @ w_qkv^T  (fp16 2-term)
    dim3 g1(3 * DM / BN, T_LEN / BM);
    gemm_mma<<<g1, 256, G_SMEM>>>(xp, wqh, wql, qkv_p, T_LEN, 3 * DM, DM);

    // 2) norm + rope + v-scale, emit fp16 hi/lo
    dim3 gp(T_LEN / 32, NH);
    qkv_prep<<<gp, 256>>>(qw, kw, cosb, sinb);

    // 3) tensor-core windowed attention -> att (fp16)
    dim3 ga(T_LEN / 128, NH);
    attn_mma<<<ga, 256, A_SMEM>>>();

    // 4) out = att @ w_o^T  (fp16 2-term)
    dim3 g2(DM / BN, T_LEN / BM);
    gemm_mma<<<g2, 256, G_SMEM>>>(atp, woh, wol, out, T_LEN, DM, DM);
}